// round 14
// baseline (speedup 1.0000x reference)
#include <cuda_runtime.h>
#include <cuda_fp16.h>
#include <cstdint>
#include <math.h>

// Problem constants
#define BB   8
#define LL   1024
#define DD   1024
#define HH   16
#define HDIM 64
#define MTOT (BB*LL)
#define WPS  ((size_t)(DD/2) * DD)
#define SCALE_Q (0.03125f * 1.44269504088896340736f)   // (1/sqrt(D)) * log2(e)

// ---------------------------------------------------------------------------
// Scratch (device globals)
// ---------------------------------------------------------------------------
__device__ float g_zinv[(size_t)BB * HH * LL];      // 512 KB (1/Z)
__device__ float g_sz[(size_t)BB * HH];             // sum_k zinv
__device__ float g_sx[(size_t)BB * HH * DD];        // 512 KB (sum_k x_v * zinv)
__device__ float g_Sv[(size_t)BB * HH * HDIM];      // 32 KB  (exact sum_k V/Z)
__device__ __half g_Ah[(size_t)MTOT * DD];          // 16 MB (x_q fp16 / attn out)
__device__ __half g_Xk[(size_t)MTOT * DD];          // 16 MB (x_k fp16)
__device__ __half g_Xv[(size_t)MTOT * DD];          // 16 MB (x_v fp16)
__device__ uint32_t g_Wp[(size_t)4 * (DD/2) * DD];  // 8 MB (4 W's k-pair fp16x2)
__device__ __half g_Qh[(size_t)MTOT * DD];          // 16 MB (Q*log2e/32, fp16)
__device__ __half g_Kh[(size_t)MTOT * DD];          // 16 MB
__device__ uint32_t g_Vph[(size_t)BB * HH * (LL/2) * HDIM];  // 16 MB (1024*V/Z k-pair)

// ---------------------------------------------------------------------------
// Helpers
// ---------------------------------------------------------------------------
__device__ __forceinline__ void mma16816(float c[4],
    uint32_t a0, uint32_t a1, uint32_t a2, uint32_t a3,
    uint32_t b0, uint32_t b1)
{
    asm volatile(
        "mma.sync.aligned.m16n8k16.row.col.f32.f16.f16.f32 "
        "{%0,%1,%2,%3}, {%4,%5,%6,%7}, {%8,%9}, {%0,%1,%2,%3};"
        : "+f"(c[0]), "+f"(c[1]), "+f"(c[2]), "+f"(c[3])
        : "r"(a0), "r"(a1), "r"(a2), "r"(a3), "r"(b0), "r"(b1));
}

__device__ __forceinline__ void ldsm4(uint32_t r[4], uint32_t addr)
{
    asm volatile(
        "ldmatrix.sync.aligned.m8n8.x4.shared.b16 {%0,%1,%2,%3}, [%4];"
        : "=r"(r[0]), "=r"(r[1]), "=r"(r[2]), "=r"(r[3]) : "r"(addr));
}

__device__ __forceinline__ uint32_t smem_u32(const void* p) {
    uint32_t a;
    asm("{ .reg .u64 t; cvta.to.shared.u64 t, %1; cvt.u32.u64 %0, t; }"
        : "=r"(a) : "l"(p));
    return a;
}

#define CP_ASYNC16(dst_u32, src_ptr) \
    asm volatile("cp.async.cg.shared.global [%0], [%1], 16;" \
        :: "r"(dst_u32), "l"(src_ptr) : "memory")
#define CP_COMMIT() asm volatile("cp.async.commit_group;" ::: "memory")
#define CP_WAIT(n)  asm volatile("cp.async.wait_group %0;" :: "n"(n) : "memory")

__device__ __forceinline__ uint32_t pack_h2(float x, float y) {
    __half2 p = __floats2half2_rn(x, y);   // .x = x (low half)
    return *(uint32_t*)&p;
}

// ---------------------------------------------------------------------------
// fp32 -> fp16, batched over 3 inputs (blockIdx.y selects)
// ---------------------------------------------------------------------------
__global__ __launch_bounds__(256) void tof16_batch(
    const float* __restrict__ x0, const float* __restrict__ x1,
    const float* __restrict__ x2,
    __half* __restrict__ h0, __half* __restrict__ h1, __half* __restrict__ h2,
    int n4)
{
    int i = blockIdx.x * blockDim.x + threadIdx.x;
    if (i >= n4) return;
    const float* x;
    __half* h;
    if (blockIdx.y == 0)      { x = x0; h = h0; }
    else if (blockIdx.y == 1) { x = x1; h = h1; }
    else                      { x = x2; h = h2; }
    float4 v = ((const float4*)x)[i];
    __half2* hp = (__half2*)h;
    hp[2*i]   = __floats2half2_rn(v.x, v.y);
    hp[2*i+1] = __floats2half2_rn(v.z, v.w);
}

// ---------------------------------------------------------------------------
// pack 4 W's [K,N] fp32 -> k-pair fp16x2 [k2][n] (blockIdx.y selects)
// ---------------------------------------------------------------------------
__global__ __launch_bounds__(256) void pack_w_batch(
    const float* __restrict__ W0, const float* __restrict__ W1,
    const float* __restrict__ W2, const float* __restrict__ W3,
    uint32_t* __restrict__ P)
{
    int i = blockIdx.x * blockDim.x + threadIdx.x;
    if (i >= (DD/2) * DD) return;
    const float* W;
    if (blockIdx.y == 0)      W = W0;
    else if (blockIdx.y == 1) W = W1;
    else if (blockIdx.y == 2) W = W2;
    else                      W = W3;
    uint32_t* Ph = P + (size_t)blockIdx.y * WPS;
    int k2 = i >> 10, n = i & (DD - 1);
    Ph[i] = pack_h2(W[(size_t)(2*k2) * DD + n], W[(size_t)(2*k2 + 1) * DD + n]);
}

// ---------------------------------------------------------------------------
// sz[bh] = sum_k zinv[bh,k]
// ---------------------------------------------------------------------------
__global__ __launch_bounds__(256) void sumz_kernel(
    const float* __restrict__ Zi, float* __restrict__ Sz)
{
    __shared__ float red[256];
    const int bh = blockIdx.x;
    const int tid = threadIdx.x;
    float s = 0.0f;
    #pragma unroll
    for (int p = 0; p < 4; p++) s += Zi[(size_t)bh * LL + tid + p * 256];
    red[tid] = s;
    __syncthreads();
    for (int w = 128; w > 0; w >>= 1) {
        if (tid < w) red[tid] += red[tid + w];
        __syncthreads();
    }
    if (tid == 0) Sz[bh] = red[0];
}

// ---------------------------------------------------------------------------
// s_x[bh][d'] = sum_k x_v[b,k,d'] * zinv[bh,k]   (exact fp32)
// ---------------------------------------------------------------------------
__global__ __launch_bounds__(256) void sx_kernel(
    const float* __restrict__ xv, const float* __restrict__ Zi,
    float* __restrict__ Sx)
{
    extern __shared__ float szi[];   // [16][1024]
    const int b = blockIdx.x;
    const int dc = blockIdx.y;       // 0..15
    const int tid = threadIdx.x;
    const int d = tid & 63;
    const int s = tid >> 6;          // k-slice 0..3

    for (int i = tid; i < 16 * 1024; i += 256)
        szi[i] = Zi[(size_t)(b * 16) * LL + i];
    __syncthreads();

    float acc[16];
    #pragma unroll
    for (int h = 0; h < 16; h++) acc[h] = 0.0f;

    const int dglob = dc * 64 + d;
    const int k0 = s * 256;
    for (int k = k0; k < k0 + 256; k++) {
        float x = xv[((size_t)b * LL + k) * DD + dglob];
        #pragma unroll
        for (int h = 0; h < 16; h++)
            acc[h] = fmaf(x, szi[h * 1024 + k], acc[h]);
    }
    __syncthreads();
    float* red = szi;   // [4][16][64]
    #pragma unroll
    for (int h = 0; h < 16; h++)
        red[(s * 16 + h) * 64 + d] = acc[h];
    __syncthreads();
    for (int i = tid; i < 16 * 64; i += 256) {
        int h = i >> 6, dd = i & 63;
        float v = red[(0 * 16 + h) * 64 + dd] + red[(1 * 16 + h) * 64 + dd]
                + red[(2 * 16 + h) * 64 + dd] + red[(3 * 16 + h) * 64 + dd];
        Sx[(size_t)(b * 16 + h) * DD + dc * 64 + dd] = v;
    }
}

// ---------------------------------------------------------------------------
// Sv[bh][d] = sum_{d'} s_x[bh][d'] * Wv[d'][h*64+d] + bv[h*64+d]*sz[bh]
// ---------------------------------------------------------------------------
__global__ __launch_bounds__(256) void sv_kernel(
    const float* __restrict__ Sx, const float* __restrict__ Wv,
    const float* __restrict__ bv, const float* __restrict__ Sz,
    float* __restrict__ Sv)
{
    __shared__ float sxr[1024];
    __shared__ float red[4 * 64];
    const int bh = blockIdx.x;
    const int h = bh & 15;
    const int tid = threadIdx.x;
    const int d = tid & 63;
    const int s = tid >> 6;

    for (int i = tid; i < 1024; i += 256)
        sxr[i] = Sx[(size_t)bh * DD + i];
    __syncthreads();

    float acc = 0.0f;
    const int k0 = s * 256;
    const int col = h * HDIM + d;
    for (int k = k0; k < k0 + 256; k++)
        acc = fmaf(sxr[k], Wv[(size_t)k * DD + col], acc);
    red[s * 64 + d] = acc;
    __syncthreads();
    if (tid < 64)
        Sv[(size_t)bh * HDIM + d] =
            red[d] + red[64 + d] + red[128 + d] + red[192 + d] + bv[col] * Sz[bh];
}

// ---------------------------------------------------------------------------
// Single-pass fp16 HMMA GEMM, n-split into two 64-col halves for occupancy 3.
// mode 0: fp32 C = A@W + bias
// mode 1: fp16 Hout = (A@W + bias) * oscale  (gridDim.z may be 2: second set)
// mode 2: Vp pack: Vout[bh][k2][d] = fp16x2{ 1024*zi*(A@W+bias) } k-pairs
// SMEM per buffer: A 18432 + B(64 cols, pitch 288) 9216 = 27648; x2 = 55296.
// ---------------------------------------------------------------------------
#define F_AH   0
#define F_BH   18432
#define F_BUF  27648
#define F_SMEM (2 * F_BUF)

__device__ __forceinline__ void gemm1p_load(
    uint32_t sb0, int buf, int tid, int m0, int nb, int kt,
    const __half* __restrict__ Ah, const uint32_t* __restrict__ Bh)
{
    const uint32_t sb = sb0 + buf * F_BUF;
    #pragma unroll
    for (int p = 0; p < 4; p++) {
        const int idx = tid + p * 256;
        const int r = idx >> 3, c = idx & 7;
        const size_t g = (size_t)(m0 + r) * DD + kt * 64 + c * 8;
        CP_ASYNC16(sb + F_AH + r * 144 + c * 16, Ah + g);
    }
    #pragma unroll
    for (int p = 0; p < 2; p++) {
        const int idx = tid + p * 256;
        const int r = idx >> 4, c = idx & 15;   // 32 k2-rows x 16 chunks
        const size_t g = (size_t)(kt * 32 + r) * DD + nb + c * 4;
        CP_ASYNC16(sb + F_BH + r * 288 + c * 16, Bh + g);
    }
}

__global__ __launch_bounds__(256, 3) void tc_gemm_1p_kernel(
    const __half* __restrict__ Ah_, const uint32_t* __restrict__ Bh_,
    const float* __restrict__ bias_, float* __restrict__ C,
    __half* __restrict__ Hout_, const float* __restrict__ Zi,
    uint32_t* __restrict__ Vout, float oscale_, int mode,
    const __half* __restrict__ Ah2, const float* __restrict__ bias2,
    __half* __restrict__ Hout2, float oscale2)
{
    const __half* Ah = Ah_;
    const uint32_t* Bh = Bh_;
    const float* bias = bias_;
    __half* Hout = Hout_;
    float oscale = oscale_;
    if (blockIdx.z == 1) {
        Ah = Ah2; Bh = Bh_ + WPS; bias = bias2; Hout = Hout2; oscale = oscale2;
    }

    extern __shared__ char sm[];
    const uint32_t smem_base = smem_u32(sm);
    const int tid = threadIdx.x;
    const int wid = tid >> 5;
    const int lane = tid & 31;
    const int g = lane >> 2;
    const int t = lane & 3;
    const int wm = wid >> 2;       // 0..1: 64-row slab
    const int wn = wid & 3;        // 0..3: 16-col slab within the 64-col half
    const int n0 = blockIdx.x * 128;
    const int m0 = blockIdx.y * 128;

    // per-lane ldmatrix base for A fragments
    const uint32_t aFrag = smem_base + F_AH
        + (wm * 64 + (lane & 15)) * 144 + (lane >> 4) * 16;

    #pragma unroll
    for (int jh = 0; jh < 2; jh++) {
        const int nb = n0 + jh * 64;

        float c[4][2][4];
        #pragma unroll
        for (int i = 0; i < 4; i++)
            #pragma unroll
            for (int j = 0; j < 2; j++)
                #pragma unroll
                for (int q = 0; q < 4; q++) c[i][j][q] = 0.0f;

        gemm1p_load(smem_base, 0, tid, m0, nb, 0, Ah, Bh);
        CP_COMMIT();

        for (int kt = 0; kt < 16; kt++) {
            const int buf = kt & 1;
            if (kt < 15) {
                gemm1p_load(smem_base, buf ^ 1, tid, m0, nb, kt + 1, Ah, Bh);
                CP_COMMIT();
                CP_WAIT(1);
            } else {
                CP_WAIT(0);
            }
            __syncthreads();

            const uint32_t aB = aFrag + buf * F_BUF;
            const char* Bb = sm + buf * F_BUF + F_BH;

            #pragma unroll
            for (int ks = 0; ks < 4; ks++) {
                uint32_t aH[4][4], bH[2][2];
                #pragma unroll
                for (int i = 0; i < 4; i++)
                    ldsm4(aH[i], aB + i * (16 * 144) + ks * 32);
                #pragma unroll
                for (int j = 0; j < 2; j++) {
                    const int off = (ks * 8 + t) * 288 + (wn * 16 + j * 8 + g) * 4;
                    bH[j][0] = *(const uint32_t*)(Bb + off);
                    bH[j][1] = *(const uint32_t*)(Bb + off + 4 * 288);
                }
                #pragma unroll
                for (int i = 0; i < 4; i++)
                    #pragma unroll
                    for (int j = 0; j < 2; j++)
                        mma16816(c[i][j], aH[i][0], aH[i][1], aH[i][2], aH[i][3],
                                 bH[j][0], bH[j][1]);
            }
            __syncthreads();
        }

        if (mode == 2) {
            // This 64-col half is exactly one head. Stage fp32 tile, repack
            // as zinv-scaled fp16 k-pairs. stage pitch 66 floats.
            float* stage = (float*)sm;             // 128 x 66 fp32 = 33792 B
            float* ziS   = (float*)(sm + 33792);   // [128] fp32
            #pragma unroll
            for (int j = 0; j < 2; j++) {
                const int cl = wn * 16 + j * 8 + 2 * t;
                const float2 bv = *(const float2*)(bias + nb + cl);
                #pragma unroll
                for (int i = 0; i < 4; i++) {
                    const int rl = wm * 64 + i * 16 + g;
                    stage[rl * 66 + cl]       = c[i][j][0] + bv.x;
                    stage[rl * 66 + cl + 1]   = c[i][j][1] + bv.y;
                    stage[(rl + 8) * 66 + cl]     = c[i][j][2] + bv.x;
                    stage[(rl + 8) * 66 + cl + 1] = c[i][j][3] + bv.y;
                }
            }
            const int b = m0 >> 10;
            const int l0 = m0 & 1023;
            const int h = nb >> 6;
            if (tid < 128)
                ziS[tid] = Zi[(size_t)(b * 16 + h) * LL + l0 + tid] * 1024.0f;
            __syncthreads();
            const int k20 = l0 >> 1;
            #pragma unroll
            for (int p = 0; p < 16; p++) {
                const int i = tid + p * 256;      // 0..4095
                const int k2r = i >> 6;
                const int d = i & 63;
                float v0 = stage[(2 * k2r) * 66 + d] * ziS[2 * k2r];
                float v1 = stage[(2 * k2r + 1) * 66 + d] * ziS[2 * k2r + 1];
                Vout[((size_t)(b * 16 + h) * 512 + k20 + k2r) * 64 + d] =
                    pack_h2(v0, v1);
            }
            __syncthreads();   // stage reused by next half
            continue;
        }

        #pragma unroll
        for (int j = 0; j < 2; j++) {
            const int col = nb + wn * 16 + j * 8 + 2 * t;
            const float2 bv = *(const float2*)(bias + col);
            #pragma unroll
            for (int i = 0; i < 4; i++) {
                const int row = m0 + wm * 64 + i * 16 + g;
                float v0 = c[i][j][0] + bv.x, v1 = c[i][j][1] + bv.y;
                float v2 = c[i][j][2] + bv.x, v3 = c[i][j][3] + bv.y;
                if (mode == 0) {
                    float* o = C + (size_t)row * DD + col;
                    *(float2*)o = make_float2(v0, v1);
                    *(float2*)(o + 8 * DD) = make_float2(v2, v3);
                } else {
                    *(uint32_t*)(Hout + (size_t)row * DD + col) =
                        pack_h2(v0 * oscale, v1 * oscale);
                    *(uint32_t*)(Hout + (size_t)(row + 8) * DD + col) =
                        pack_h2(v2 * oscale, v3 * oscale);
                }
            }
        }
    }
}

// ---------------------------------------------------------------------------
// HMMA colsum (fp16, ldmatrix, register-lean): zinv = 1/sum_q exp2(S')
// acc reused across the 4 row-blocks -> 3 CTAs/SM.
// ---------------------------------------------------------------------------
#define CS_KH  0
#define CS_QH  18432
#define CS_RED 36864
#define CS_SMEM 37888

__global__ __launch_bounds__(256, 3) void attn_colsum_tc(
    const __half* __restrict__ Qh, const __half* __restrict__ Kh,
    float* __restrict__ zinv)
{
    extern __shared__ char sm[];
    const uint32_t sb = smem_u32(sm);
    const int tid = threadIdx.x;
    const int wid = tid >> 5;
    const int lane = tid & 31;
    const int g = lane >> 2;
    const int t = lane & 3;
    const int wm = wid >> 2;
    const int wn = wid & 3;
    const int kt = blockIdx.x;
    const int bh = blockIdx.y;
    const int b = bh >> 4, h = bh & 15;

    // ldmatrix bases
    const uint32_t aFrag = sb + CS_QH
        + (wm * 64 + (lane & 15)) * 144 + (lane >> 4) * 16;
    const uint32_t bFrag = sb + CS_KH
        + (wn * 32 + ((lane >> 4) << 3) + (lane & 7)) * 144 + ((lane >> 3) & 1) * 16;

    #pragma unroll
    for (int p = 0; p < 4; p++) {
        const int idx = tid + p * 256;
        const int r = idx >> 3, c = idx & 7;
        const size_t go = ((size_t)(b * LL + kt * 128 + r)) * DD + h * HDIM + c * 8;
        CP_ASYNC16(sb + CS_KH + r * 144 + c * 16, Kh + go);
    }
    #pragma unroll
    for (int p = 0; p < 4; p++) {
        const int idx = tid + p * 256;
        const int r = idx >> 3, c = idx & 7;
        const size_t go = ((size_t)(b * LL + r)) * DD + h * HDIM + c * 8;
        CP_ASYNC16(sb + CS_QH + r * 144 + c * 16, Qh + go);
    }
    CP_COMMIT();

    float cs[4][2];
    #pragma unroll
    for (int j = 0; j < 4; j++) { cs[j][0] = 0.0f; cs[j][1] = 0.0f; }

    for (int qt = 0; qt < 8; qt++) {
        CP_WAIT(0);
        __syncthreads();

        #pragma unroll
        for (int i = 0; i < 4; i++) {
            float acc[4][4];
            #pragma unroll
            for (int j = 0; j < 4; j++)
                #pragma unroll
                for (int q = 0; q < 4; q++) acc[j][q] = 0.0f;

            #pragma unroll
            for (int ks = 0; ks < 4; ks++) {
                uint32_t aH[4], bf[2][4];
                ldsm4(aH, aFrag + i * (16 * 144) + ks * 32);
                #pragma unroll
                for (int j2 = 0; j2 < 2; j2++)
                    ldsm4(bf[j2], bFrag + j2 * (16 * 144) + ks * 32);
                #pragma unroll
                for (int j = 0; j < 4; j++)
                    mma16816(acc[j], aH[0], aH[1], aH[2], aH[3],
                             bf[j >> 1][2 * (j & 1)], bf[j >> 1][2 * (j & 1) + 1]);
            }
            #pragma unroll
            for (int j = 0; j < 4; j++) {
                cs[j][0] += exp2f(acc[j][0]) + exp2f(acc[j][2]);
                cs[j][1] += exp2f(acc[j][1]) + exp2f(acc[j][3]);
            }
        }

        __syncthreads();
        if (qt < 7) {
            #pragma unroll
            for (int p = 0; p < 4; p++) {
                const int idx = tid + p * 256;
                const int r = idx >> 3, c = idx & 7;
                const size_t go = ((size_t)(b * LL + (qt + 1) * 128 + r)) * DD + h * HDIM + c * 8;
                CP_ASYNC16(sb + CS_QH + r * 144 + c * 16, Qh + go);
            }
            CP_COMMIT();
        }
    }

    float* red = (float*)(sm + CS_RED);
    #pragma unroll
    for (int j = 0; j < 4; j++)
        #pragma unroll
        for (int hh = 0; hh < 2; hh++) {
            float v = cs[j][hh];
            v += __shfl_down_sync(0xffffffffu, v, 16);
            v += __shfl_down_sync(0xffffffffu, v, 8);
            v += __shfl_down_sync(0xffffffffu, v, 4);
            if (g == 0) red[wid * 32 + j * 8 + 2 * t + hh] = v;
        }
    __syncthreads();
    if (tid < 128) {
        const int col = tid;
        const int w2 = col >> 5, cl = col & 31;
        zinv[(size_t)bh * LL + kt * 128 + col] =
            1.0f / (red[w2 * 32 + cl] + red[(w2 + 4) * 32 + cl]);
    }
}

// ---------------------------------------------------------------------------
// HMMA AV (E = 1 + e): out = Sv + (1/1024) * sum_k e * (1024*Vp), e=exp2(S')-1
// 64-row q tiles, occupancy 2. Grid (16, 128), 256 thr.
// ---------------------------------------------------------------------------
#define AV_QH   0
#define AV_KH   9216
#define AV_E    27648
#define AV_VP0  45056
#define AV_VPB  17408
#define AV_SMEM 79872

__device__ __forceinline__ void av_load_kvp(
    uint32_t sb, int tid, int b, int h, int bh, int kt, int buf,
    const __half* __restrict__ Kh, const uint32_t* __restrict__ Vph)
{
    #pragma unroll
    for (int p = 0; p < 4; p++) {
        const int idx = tid + p * 256;
        const int r = idx >> 3, c = idx & 7;
        const size_t go = ((size_t)(b * LL + kt * 128 + r)) * DD + h * HDIM + c * 8;
        CP_ASYNC16(sb + AV_KH + r * 144 + c * 16, Kh + go);
    }
    const uint32_t vb = sb + AV_VP0 + buf * AV_VPB;
    #pragma unroll
    for (int p = 0; p < 4; p++) {
        const int idx = tid + p * 256;
        const int r = idx >> 4, c = idx & 15;
        const size_t go = ((size_t)bh * 512 + kt * 64 + r) * 64 + c * 4;
        CP_ASYNC16(vb + r * 272 + c * 16, Vph + go);
    }
}

__global__ __launch_bounds__(256, 2) void attn_av_tc(
    const __half* __restrict__ Qh, const __half* __restrict__ Kh,
    const uint32_t* __restrict__ Vph, const float* __restrict__ Sv,
    __half* __restrict__ Oh)
{
    extern __shared__ char sm[];
    const uint32_t sb = smem_u32(sm);
    const int tid = threadIdx.x;
    const int wid = tid >> 5;
    const int lane = tid & 31;
    const int g = lane >> 2;
    const int t = lane & 3;
    const int wm = wid >> 2;       // 0..1: 32-row slab
    const int wn = wid & 3;        // 0..3: 32-col (S) / 16-col (out) slab
    const int qt = blockIdx.x;     // 0..15, 64-row q tiles
    const int bh = blockIdx.y;
    const int b = bh >> 4, h = bh & 15;

    // ldmatrix bases
    const uint32_t aFragQ = sb + AV_QH
        + (wm * 32 + (lane & 15)) * 144 + (lane >> 4) * 16;
    const uint32_t bFragK = sb + AV_KH
        + (wn * 32 + ((lane >> 4) << 3) + (lane & 7)) * 144 + ((lane >> 3) & 1) * 16;
    const uint32_t eFrag = sb + AV_E
        + (wm * 32 + (lane & 15)) * 272 + (lane >> 4) * 16;

    // load Q tile 64x64 fp16 (512 chunks)
    #pragma unroll
    for (int p = 0; p < 2; p++) {
        const int idx = tid + p * 256;
        const int r = idx >> 3, c = idx & 7;
        const size_t go = ((size_t)(b * LL + qt * 64 + r)) * DD + h * HDIM + c * 8;
        CP_ASYNC16(sb + AV_QH + r * 144 + c * 16, Qh + go);
    }
    av_load_kvp(sb, tid, b, h, bh, 0, 0, Kh, Vph);
    CP_COMMIT();

    float out[2][2][4];
    #pragma unroll
    for (int i = 0; i < 2; i++)
        #pragma unroll
        for (int j = 0; j < 2; j++)
            #pragma unroll
            for (int q = 0; q < 4; q++) out[i][j][q] = 0.0f;

    for (int kt = 0; kt < 8; kt++) {
        const int buf = kt & 1;
        CP_WAIT(0);
        __syncthreads();

        // ---- GEMM1: S (64x128) = Q . K^T ----
        float acc[2][4][4];
        #pragma unroll
        for (int i = 0; i < 2; i++)
            #pragma unroll
            for (int j = 0; j < 4; j++)
                #pragma unroll
                for (int q = 0; q < 4; q++) acc[i][j][q] = 0.0f;

        #pragma unroll
        for (int ks = 0; ks < 4; ks++) {
            uint32_t aH[2][4], bf[2][4];
            #pragma unroll
            for (int i = 0; i < 2; i++)
                ldsm4(aH[i], aFragQ + i * (16 * 144) + ks * 32);
            #pragma unroll
            for (int j2 = 0; j2 < 2; j2++)
                ldsm4(bf[j2], bFragK + j2 * (16 * 144) + ks * 32);
            #pragma unroll
            for (int i = 0; i < 2; i++)
                #pragma unroll
                for (int j = 0; j < 4; j++)
                    mma16816(acc[i][j], aH[i][0], aH[i][1], aH[i][2], aH[i][3],
                             bf[j >> 1][2 * (j & 1)], bf[j >> 1][2 * (j & 1) + 1]);
        }

        // ---- e = exp2(S') - 1 -> smem (pitch 272) ----
        #pragma unroll
        for (int i = 0; i < 2; i++) {
            const int row = wm * 32 + i * 16 + g;
            #pragma unroll
            for (int j = 0; j < 4; j++) {
                const int colb = (wn * 32 + j * 8 + 2 * t) * 2;
                float e0 = exp2f(acc[i][j][0]) - 1.0f;
                float e1 = exp2f(acc[i][j][1]) - 1.0f;
                float e2 = exp2f(acc[i][j][2]) - 1.0f;
                float e3 = exp2f(acc[i][j][3]) - 1.0f;
                *(uint32_t*)(sm + AV_E + row * 272 + colb) = pack_h2(e0, e1);
                *(uint32_t*)(sm + AV_E + (row + 8) * 272 + colb) = pack_h2(e2, e3);
            }
        }
        __syncthreads();

        if (kt < 7) {
            av_load_kvp(sb, tid, b, h, bh, kt + 1, buf ^ 1, Kh, Vph);
            CP_COMMIT();
        }

        // ---- GEMM2: out (64x64) += e . Vp ----
        const char* VH = sm + AV_VP0 + buf * AV_VPB;
        #pragma unroll
        for (int ks = 0; ks < 8; ks++) {
            uint32_t aE[2][4], bV[2][2];
            #pragma unroll
            for (int i = 0; i < 2; i++)
                ldsm4(aE[i], eFrag + i * (16 * 272) + ks * 32);
            #pragma unroll
            for (int j = 0; j < 2; j++) {
                const int off = (ks * 8 + t) * 272 + (wn * 16 + j * 8 + g) * 4;
                bV[j][0] = *(const uint32_t*)(VH + off);
                bV[j][1] = *(const uint32_t*)(VH + off + 4 * 272);
            }
            #pragma unroll
            for (int i = 0; i < 2; i++)
                #pragma unroll
                for (int j = 0; j < 2; j++)
                    mma16816(out[i][j], aE[i][0], aE[i][1], aE[i][2], aE[i][3],
                             bV[j][0], bV[j][1]);
        }
        __syncthreads();
    }

    const float s = 1.0f / 1024.0f;
    #pragma unroll
    for (int i = 0; i < 2; i++) {
        const int row = qt * 64 + wm * 32 + i * 16 + g;
        #pragma unroll
        for (int j = 0; j < 2; j++) {
            const int dcol = wn * 16 + j * 8 + 2 * t;
            const float sv0 = Sv[(size_t)bh * HDIM + dcol];
            const float sv1 = Sv[(size_t)bh * HDIM + dcol + 1];
            const size_t o0 = ((size_t)b * LL + row) * DD + h * HDIM + dcol;
            const size_t o1 = ((size_t)b * LL + row + 8) * DD + h * HDIM + dcol;
            *(uint32_t*)(Oh + o0) =
                pack_h2(out[i][j][0] * s + sv0, out[i][j][1] * s + sv1);
            *(uint32_t*)(Oh + o1) =
                pack_h2(out[i][j][2] * s + sv0, out[i][j][3] * s + sv1);
        }
    }
}

// ---------------------------------------------------------------------------
// Launch
// ---------------------------------------------------------------------------
extern "C" void kernel_launch(void* const* d_in, const int* in_sizes, int n_in,
                              void* d_out, int out_size)
{
    (void)in_sizes; (void)n_in; (void)out_size;

    const float* x_q = (const float*)d_in[0];
    const float* x_k = (const float*)d_in[1];
    const float* x_v = (const float*)d_in[2];
    // d_in[3] = mask: unused (reference never applies it)
    const float* Wq  = (const float*)d_in[4];
    const float* bq  = (const float*)d_in[5];
    const float* Wk  = (const float*)d_in[6];
    const float* bk  = (const float*)d_in[7];
    const float* Wv  = (const float*)d_in[8];
    const float* bv  = (const float*)d_in[9];
    const float* Wo  = (const float*)d_in[10];
    const float* bo  = (const float*)d_in[11];

    float *pZi, *pSz, *pSx, *pSv;
    __half *pAh, *pXk, *pXv, *pQh, *pKh;
    uint32_t *pWp, *pVh;
    cudaGetSymbolAddress((void**)&pZi, g_zinv);
    cudaGetSymbolAddress((void**)&pSz, g_sz);
    cudaGetSymbolAddress((void**)&pSx, g_sx);
    cudaGetSymbolAddress((void**)&pSv, g_Sv);
    cudaGetSymbolAddress((void**)&pAh, g_Ah);
    cudaGetSymbolAddress((void**)&pXk, g_Xk);
    cudaGetSymbolAddress((void**)&pXv, g_Xv);
    cudaGetSymbolAddress((void**)&pWp, g_Wp);
    cudaGetSymbolAddress((void**)&pQh, g_Qh);
    cudaGetSymbolAddress((void**)&pKh, g_Kh);
    cudaGetSymbolAddress((void**)&pVh, g_Vph);

    cudaFuncSetAttribute(tc_gemm_1p_kernel,
                         cudaFuncAttributeMaxDynamicSharedMemorySize, F_SMEM);
    cudaFuncSetAttribute(attn_colsum_tc,
                         cudaFuncAttributeMaxDynamicSharedMemorySize, CS_SMEM);
    cudaFuncSetAttribute(attn_av_tc,
                         cudaFuncAttributeMaxDynamicSharedMemorySize, AV_SMEM);
    cudaFuncSetAttribute(sx_kernel,
                         cudaFuncAttributeMaxDynamicSharedMemorySize, 65536);

    const int n4 = MTOT * DD / 4;
    const dim3 t256(256);
    const int npack = (DD / 2) * DD;
    const dim3 gGemm(DD / 128, MTOT / 128, 1);
    const dim3 gGemmQK(DD / 128, MTOT / 128, 2);

    // All fp32->fp16 conversions and W packs, batched
    tof16_batch<<<dim3((n4 + 255) / 256, 3), t256>>>(
        x_q, x_k, x_v, pAh, pXk, pXv, n4);
    pack_w_batch<<<dim3((npack + 255) / 256, 4), t256>>>(Wq, Wk, Wv, Wo, pWp);

    // Q + K projections in one launch (z=0: Q scaled log2e/32; z=1: K)
    tc_gemm_1p_kernel<<<gGemmQK, 256, F_SMEM>>>(
        pAh, pWp, bq, nullptr, pQh, nullptr, nullptr, SCALE_Q, 1,
        pXk, bk, pKh, 1.0f);

    // zinv = 1 / column-softmax sums (needs only Qh, Kh)
    attn_colsum_tc<<<dim3(8, BB * HH), 256, CS_SMEM>>>(pQh, pKh, pZi);

    // Exact Sv via commuted identity: Sv = (sum_k x_v zi) @ Wv + bv * sum(zi)
    sumz_kernel<<<BB * HH, 256>>>(pZi, pSz);
    sx_kernel<<<dim3(BB, 16), 256, 65536>>>(x_v, pZi, pSx);
    sv_kernel<<<BB * HH, 256>>>(pSx, Wv, bv, pSz, pSv);

    // V projection fused with Vp pack (mode 2): writes 1024*V/Z k-pairs
    tc_gemm_1p_kernel<<<gGemm, 256, F_SMEM>>>(
        pXv, pWp + 2 * WPS, bv, nullptr, nullptr, pZi, pVh, 1.0f, 2,
        nullptr, nullptr, nullptr, 0.0f);

    // AV -> fp16 attention output in g_Ah
    attn_av_tc<<<dim3(16, BB * HH), 256, AV_SMEM>>>(pQh, pKh, pVh, pSv, pAh);

    // Output projection (mode 0) -> d_out
    tc_gemm_1p_kernel<<<gGemm, 256, F_SMEM>>>(
        pAh, pWp + 3 * WPS, bo, (float*)d_out, nullptr, nullptr, nullptr, 1.0f, 0,
        nullptr, nullptr, nullptr, 0.0f);
}

// round 15
// speedup vs baseline: 1.0675x; 1.0675x over previous
#include <cuda_runtime.h>
#include <cuda_fp16.h>
#include <cstdint>
#include <math.h>

// Problem constants
#define BB   8
#define LL   1024
#define DD   1024
#define HH   16
#define HDIM 64
#define MTOT (BB*LL)
#define WPS  ((size_t)(DD/2) * DD)
#define SCALE_Q (0.03125f * 1.44269504088896340736f)   // (1/sqrt(D)) * log2(e)

// ---------------------------------------------------------------------------
// Scratch (device globals)
// ---------------------------------------------------------------------------
__device__ float g_zinv[(size_t)BB * HH * LL];      // 512 KB (1/Z)
__device__ float g_sz[(size_t)BB * HH];             // sum_k zinv
__device__ float g_sx[(size_t)BB * HH * DD];        // 512 KB (sum_k x_v * zinv)
__device__ float g_Sv[(size_t)BB * HH * HDIM];      // 32 KB  (exact sum_k V/Z)
__device__ __half g_Ah[(size_t)MTOT * DD];          // 16 MB (x_q fp16 / attn out)
__device__ __half g_Xk[(size_t)MTOT * DD];          // 16 MB (x_k fp16)
__device__ __half g_Xv[(size_t)MTOT * DD];          // 16 MB (x_v fp16)
__device__ uint32_t g_Wp[(size_t)4 * (DD/2) * DD];  // 8 MB (4 W's k-pair fp16x2)
__device__ __half g_Qh[(size_t)MTOT * DD];          // 16 MB (Q*log2e/32, fp16)
__device__ __half g_Kh[(size_t)MTOT * DD];          // 16 MB
__device__ uint32_t g_Vph[(size_t)BB * HH * (LL/2) * HDIM];  // 16 MB (1024*V/Z k-pair)

// ---------------------------------------------------------------------------
// Helpers
// ---------------------------------------------------------------------------
__device__ __forceinline__ void mma16816(float c[4],
    uint32_t a0, uint32_t a1, uint32_t a2, uint32_t a3,
    uint32_t b0, uint32_t b1)
{
    asm volatile(
        "mma.sync.aligned.m16n8k16.row.col.f32.f16.f16.f32 "
        "{%0,%1,%2,%3}, {%4,%5,%6,%7}, {%8,%9}, {%0,%1,%2,%3};"
        : "+f"(c[0]), "+f"(c[1]), "+f"(c[2]), "+f"(c[3])
        : "r"(a0), "r"(a1), "r"(a2), "r"(a3), "r"(b0), "r"(b1));
}

__device__ __forceinline__ void ldsm4(uint32_t r[4], uint32_t addr)
{
    asm volatile(
        "ldmatrix.sync.aligned.m8n8.x4.shared.b16 {%0,%1,%2,%3}, [%4];"
        : "=r"(r[0]), "=r"(r[1]), "=r"(r[2]), "=r"(r[3]) : "r"(addr));
}

__device__ __forceinline__ uint32_t smem_u32(const void* p) {
    uint32_t a;
    asm("{ .reg .u64 t; cvta.to.shared.u64 t, %1; cvt.u32.u64 %0, t; }"
        : "=r"(a) : "l"(p));
    return a;
}

#define CP_ASYNC16(dst_u32, src_ptr) \
    asm volatile("cp.async.cg.shared.global [%0], [%1], 16;" \
        :: "r"(dst_u32), "l"(src_ptr) : "memory")
#define CP_COMMIT() asm volatile("cp.async.commit_group;" ::: "memory")
#define CP_WAIT(n)  asm volatile("cp.async.wait_group %0;" :: "n"(n) : "memory")

__device__ __forceinline__ uint32_t pack_h2(float x, float y) {
    __half2 p = __floats2half2_rn(x, y);   // .x = x (low half)
    return *(uint32_t*)&p;
}

// ---------------------------------------------------------------------------
// fp32 -> fp16, batched over 3 inputs (blockIdx.y selects)
// ---------------------------------------------------------------------------
__global__ __launch_bounds__(256) void tof16_batch(
    const float* __restrict__ x0, const float* __restrict__ x1,
    const float* __restrict__ x2,
    __half* __restrict__ h0, __half* __restrict__ h1, __half* __restrict__ h2,
    int n4)
{
    int i = blockIdx.x * blockDim.x + threadIdx.x;
    if (i >= n4) return;
    const float* x;
    __half* h;
    if (blockIdx.y == 0)      { x = x0; h = h0; }
    else if (blockIdx.y == 1) { x = x1; h = h1; }
    else                      { x = x2; h = h2; }
    float4 v = ((const float4*)x)[i];
    __half2* hp = (__half2*)h;
    hp[2*i]   = __floats2half2_rn(v.x, v.y);
    hp[2*i+1] = __floats2half2_rn(v.z, v.w);
}

// ---------------------------------------------------------------------------
// pack 4 W's [K,N] fp32 -> k-pair fp16x2 [k2][n] (blockIdx.y selects)
// ---------------------------------------------------------------------------
__global__ __launch_bounds__(256) void pack_w_batch(
    const float* __restrict__ W0, const float* __restrict__ W1,
    const float* __restrict__ W2, const float* __restrict__ W3,
    uint32_t* __restrict__ P)
{
    int i = blockIdx.x * blockDim.x + threadIdx.x;
    if (i >= (DD/2) * DD) return;
    const float* W;
    if (blockIdx.y == 0)      W = W0;
    else if (blockIdx.y == 1) W = W1;
    else if (blockIdx.y == 2) W = W2;
    else                      W = W3;
    uint32_t* Ph = P + (size_t)blockIdx.y * WPS;
    int k2 = i >> 10, n = i & (DD - 1);
    Ph[i] = pack_h2(W[(size_t)(2*k2) * DD + n], W[(size_t)(2*k2 + 1) * DD + n]);
}

// ---------------------------------------------------------------------------
// sz[bh] = sum_k zinv[bh,k]
// ---------------------------------------------------------------------------
__global__ __launch_bounds__(256) void sumz_kernel(
    const float* __restrict__ Zi, float* __restrict__ Sz)
{
    __shared__ float red[256];
    const int bh = blockIdx.x;
    const int tid = threadIdx.x;
    float s = 0.0f;
    #pragma unroll
    for (int p = 0; p < 4; p++) s += Zi[(size_t)bh * LL + tid + p * 256];
    red[tid] = s;
    __syncthreads();
    for (int w = 128; w > 0; w >>= 1) {
        if (tid < w) red[tid] += red[tid + w];
        __syncthreads();
    }
    if (tid == 0) Sz[bh] = red[0];
}

// ---------------------------------------------------------------------------
// s_x[bh][d'] = sum_k x_v[b,k,d'] * zinv[bh,k]   (exact fp32)
// ---------------------------------------------------------------------------
__global__ __launch_bounds__(256) void sx_kernel(
    const float* __restrict__ xv, const float* __restrict__ Zi,
    float* __restrict__ Sx)
{
    extern __shared__ float szi[];   // [16][1024]
    const int b = blockIdx.x;
    const int dc = blockIdx.y;       // 0..15
    const int tid = threadIdx.x;
    const int d = tid & 63;
    const int s = tid >> 6;          // k-slice 0..3

    for (int i = tid; i < 16 * 1024; i += 256)
        szi[i] = Zi[(size_t)(b * 16) * LL + i];
    __syncthreads();

    float acc[16];
    #pragma unroll
    for (int h = 0; h < 16; h++) acc[h] = 0.0f;

    const int dglob = dc * 64 + d;
    const int k0 = s * 256;
    for (int k = k0; k < k0 + 256; k++) {
        float x = xv[((size_t)b * LL + k) * DD + dglob];
        #pragma unroll
        for (int h = 0; h < 16; h++)
            acc[h] = fmaf(x, szi[h * 1024 + k], acc[h]);
    }
    __syncthreads();
    float* red = szi;   // [4][16][64]
    #pragma unroll
    for (int h = 0; h < 16; h++)
        red[(s * 16 + h) * 64 + d] = acc[h];
    __syncthreads();
    for (int i = tid; i < 16 * 64; i += 256) {
        int h = i >> 6, dd = i & 63;
        float v = red[(0 * 16 + h) * 64 + dd] + red[(1 * 16 + h) * 64 + dd]
                + red[(2 * 16 + h) * 64 + dd] + red[(3 * 16 + h) * 64 + dd];
        Sx[(size_t)(b * 16 + h) * DD + dc * 64 + dd] = v;
    }
}

// ---------------------------------------------------------------------------
// Sv[bh][d] = sum_{d'} s_x[bh][d'] * Wv[d'][h*64+d] + bv[h*64+d]*sz[bh]
// ---------------------------------------------------------------------------
__global__ __launch_bounds__(256) void sv_kernel(
    const float* __restrict__ Sx, const float* __restrict__ Wv,
    const float* __restrict__ bv, const float* __restrict__ Sz,
    float* __restrict__ Sv)
{
    __shared__ float sxr[1024];
    __shared__ float red[4 * 64];
    const int bh = blockIdx.x;
    const int h = bh & 15;
    const int tid = threadIdx.x;
    const int d = tid & 63;
    const int s = tid >> 6;

    for (int i = tid; i < 1024; i += 256)
        sxr[i] = Sx[(size_t)bh * DD + i];
    __syncthreads();

    float acc = 0.0f;
    const int k0 = s * 256;
    const int col = h * HDIM + d;
    for (int k = k0; k < k0 + 256; k++)
        acc = fmaf(sxr[k], Wv[(size_t)k * DD + col], acc);
    red[s * 64 + d] = acc;
    __syncthreads();
    if (tid < 64)
        Sv[(size_t)bh * HDIM + d] =
            red[d] + red[64 + d] + red[128 + d] + red[192 + d] + bv[col] * Sz[bh];
}

// ---------------------------------------------------------------------------
// Single-pass fp16 HMMA GEMM (R12 config: 128-col tile, ldmatrix A, occ 2).
// mode 0: fp32 C = A@W + bias
// mode 1: fp16 Hout = (A@W + bias) * oscale  (gridDim.z may be 2: second set)
// mode 2: Vp pack: Vout[bh][k2][d] = fp16x2{ 1024*zi*(A@W+bias) } k-pairs
// SMEM per buffer: A 18432 + B 16896 = 35328; x2 = 70656 -> 2 CTAs/SM.
// ---------------------------------------------------------------------------
#define F_AH   0
#define F_BH   18432
#define F_BUF  35328
#define F_SMEM (2 * F_BUF)

__device__ __forceinline__ void gemm1p_load(
    uint32_t sb0, int buf, int tid, int m0, int n0, int kt,
    const __half* __restrict__ Ah, const uint32_t* __restrict__ Bh)
{
    const uint32_t sb = sb0 + buf * F_BUF;
    #pragma unroll
    for (int p = 0; p < 4; p++) {
        const int idx = tid + p * 256;
        const int r = idx >> 3, c = idx & 7;
        const size_t g = (size_t)(m0 + r) * DD + kt * 64 + c * 8;
        CP_ASYNC16(sb + F_AH + r * 144 + c * 16, Ah + g);
    }
    #pragma unroll
    for (int p = 0; p < 4; p++) {
        const int idx = tid + p * 256;
        const int r = idx >> 5, c = idx & 31;
        const size_t g = (size_t)(kt * 32 + r) * DD + n0 + c * 4;
        CP_ASYNC16(sb + F_BH + r * 528 + c * 16, Bh + g);
    }
}

__global__ __launch_bounds__(256, 2) void tc_gemm_1p_kernel(
    const __half* __restrict__ Ah_, const uint32_t* __restrict__ Bh_,
    const float* __restrict__ bias_, float* __restrict__ C,
    __half* __restrict__ Hout_, const float* __restrict__ Zi,
    uint32_t* __restrict__ Vout, float oscale_, int mode,
    const __half* __restrict__ Ah2, const float* __restrict__ bias2,
    __half* __restrict__ Hout2, float oscale2)
{
    const __half* Ah = Ah_;
    const uint32_t* Bh = Bh_;
    const float* bias = bias_;
    __half* Hout = Hout_;
    float oscale = oscale_;
    if (blockIdx.z == 1) {
        Ah = Ah2; Bh = Bh_ + WPS; bias = bias2; Hout = Hout2; oscale = oscale2;
    }

    extern __shared__ char sm[];
    const uint32_t smem_base = smem_u32(sm);
    const int tid = threadIdx.x;
    const int wid = tid >> 5;
    const int lane = tid & 31;
    const int g = lane >> 2;
    const int t = lane & 3;
    const int wm = wid >> 2;
    const int wn = wid & 3;
    const int n0 = blockIdx.x * 128;
    const int m0 = blockIdx.y * 128;

    // per-lane ldmatrix base for A fragments
    const uint32_t aFrag = smem_base + F_AH
        + (wm * 64 + (lane & 15)) * 144 + (lane >> 4) * 16;

    float c[4][4][4];
    #pragma unroll
    for (int i = 0; i < 4; i++)
        #pragma unroll
        for (int j = 0; j < 4; j++)
            #pragma unroll
            for (int q = 0; q < 4; q++) c[i][j][q] = 0.0f;

    gemm1p_load(smem_base, 0, tid, m0, n0, 0, Ah, Bh);
    CP_COMMIT();

    for (int kt = 0; kt < 16; kt++) {
        const int buf = kt & 1;
        if (kt < 15) {
            gemm1p_load(smem_base, buf ^ 1, tid, m0, n0, kt + 1, Ah, Bh);
            CP_COMMIT();
            CP_WAIT(1);
        } else {
            CP_WAIT(0);
        }
        __syncthreads();

        const uint32_t aB = aFrag + buf * F_BUF;
        const char* Bb = sm + buf * F_BUF + F_BH;

        #pragma unroll
        for (int ks = 0; ks < 4; ks++) {
            uint32_t aH[4][4], bH[4][2];
            #pragma unroll
            for (int i = 0; i < 4; i++)
                ldsm4(aH[i], aB + i * (16 * 144) + ks * 32);
            #pragma unroll
            for (int j = 0; j < 4; j++) {
                const int off = (ks * 8 + t) * 528 + (wn * 32 + j * 8 + g) * 4;
                bH[j][0] = *(const uint32_t*)(Bb + off);
                bH[j][1] = *(const uint32_t*)(Bb + off + 4 * 528);
            }
            #pragma unroll
            for (int i = 0; i < 4; i++)
                #pragma unroll
                for (int j = 0; j < 4; j++)
                    mma16816(c[i][j], aH[i][0], aH[i][1], aH[i][2], aH[i][3],
                             bH[j][0], bH[j][1]);
        }
        __syncthreads();
    }

    if (mode == 2) {
        // Stage fp32 (C + bias) tile in smem, then repack as zinv-scaled
        // fp16 k-pairs into Vp layout. stage pitch = 132 floats (528 B).
        float* stage = (float*)sm;                 // 128 x 132 fp32 = 67584 B
        float* ziS   = (float*)(sm + 67584);       // [2][128] fp32
        #pragma unroll
        for (int j = 0; j < 4; j++) {
            const int cl = wn * 32 + j * 8 + 2 * t;
            const float2 bv = *(const float2*)(bias + n0 + cl);
            #pragma unroll
            for (int i = 0; i < 4; i++) {
                const int rl = wm * 64 + i * 16 + g;
                stage[rl * 132 + cl]       = c[i][j][0] + bv.x;
                stage[rl * 132 + cl + 1]   = c[i][j][1] + bv.y;
                stage[(rl + 8) * 132 + cl]     = c[i][j][2] + bv.x;
                stage[(rl + 8) * 132 + cl + 1] = c[i][j][3] + bv.y;
            }
        }
        const int b = m0 >> 10;
        const int l0 = m0 & 1023;
        const int h0 = n0 >> 6;        // first of 2 heads in this col block
        {
            const int hh = tid >> 7, l = tid & 127;
            ziS[tid] = Zi[(size_t)(b * 16 + h0 + hh) * LL + l0 + l] * 1024.0f;
        }
        __syncthreads();
        const int k20 = l0 >> 1;
        #pragma unroll
        for (int p = 0; p < 32; p++) {
            const int i = tid + p * 256;          // 0..8191
            const int hh = i >> 12;
            const int k2r = (i >> 6) & 63;
            const int d = i & 63;
            float v0 = stage[(2 * k2r) * 132 + hh * 64 + d] * ziS[hh * 128 + 2 * k2r];
            float v1 = stage[(2 * k2r + 1) * 132 + hh * 64 + d] * ziS[hh * 128 + 2 * k2r + 1];
            Vout[((size_t)(b * 16 + h0 + hh) * 512 + k20 + k2r) * 64 + d] =
                pack_h2(v0, v1);
        }
        return;
    }

    #pragma unroll
    for (int j = 0; j < 4; j++) {
        const int col = n0 + wn * 32 + j * 8 + 2 * t;
        const float2 bv = *(const float2*)(bias + col);
        #pragma unroll
        for (int i = 0; i < 4; i++) {
            const int row = m0 + wm * 64 + i * 16 + g;
            float v0 = c[i][j][0] + bv.x, v1 = c[i][j][1] + bv.y;
            float v2 = c[i][j][2] + bv.x, v3 = c[i][j][3] + bv.y;
            if (mode == 0) {
                float* o = C + (size_t)row * DD + col;
                *(float2*)o = make_float2(v0, v1);
                *(float2*)(o + 8 * DD) = make_float2(v2, v3);
            } else {
                *(uint32_t*)(Hout + (size_t)row * DD + col) =
                    pack_h2(v0 * oscale, v1 * oscale);
                *(uint32_t*)(Hout + (size_t)(row + 8) * DD + col) =
                    pack_h2(v2 * oscale, v3 * oscale);
            }
        }
    }
}

// ---------------------------------------------------------------------------
// HMMA colsum (fp16, ldmatrix, register-lean): zinv = 1/sum_q exp2(S')
// acc reused across the 4 row-blocks -> 3 CTAs/SM. (R13 version — measured win)
// ---------------------------------------------------------------------------
#define CS_KH  0
#define CS_QH  18432
#define CS_RED 36864
#define CS_SMEM 37888

__global__ __launch_bounds__(256, 3) void attn_colsum_tc(
    const __half* __restrict__ Qh, const __half* __restrict__ Kh,
    float* __restrict__ zinv)
{
    extern __shared__ char sm[];
    const uint32_t sb = smem_u32(sm);
    const int tid = threadIdx.x;
    const int wid = tid >> 5;
    const int lane = tid & 31;
    const int g = lane >> 2;
    const int t = lane & 3;
    const int wm = wid >> 2;
    const int wn = wid & 3;
    const int kt = blockIdx.x;
    const int bh = blockIdx.y;
    const int b = bh >> 4, h = bh & 15;

    // ldmatrix bases
    const uint32_t aFrag = sb + CS_QH
        + (wm * 64 + (lane & 15)) * 144 + (lane >> 4) * 16;
    const uint32_t bFrag = sb + CS_KH
        + (wn * 32 + ((lane >> 4) << 3) + (lane & 7)) * 144 + ((lane >> 3) & 1) * 16;

    #pragma unroll
    for (int p = 0; p < 4; p++) {
        const int idx = tid + p * 256;
        const int r = idx >> 3, c = idx & 7;
        const size_t go = ((size_t)(b * LL + kt * 128 + r)) * DD + h * HDIM + c * 8;
        CP_ASYNC16(sb + CS_KH + r * 144 + c * 16, Kh + go);
    }
    #pragma unroll
    for (int p = 0; p < 4; p++) {
        const int idx = tid + p * 256;
        const int r = idx >> 3, c = idx & 7;
        const size_t go = ((size_t)(b * LL + r)) * DD + h * HDIM + c * 8;
        CP_ASYNC16(sb + CS_QH + r * 144 + c * 16, Qh + go);
    }
    CP_COMMIT();

    float cs[4][2];
    #pragma unroll
    for (int j = 0; j < 4; j++) { cs[j][0] = 0.0f; cs[j][1] = 0.0f; }

    for (int qt = 0; qt < 8; qt++) {
        CP_WAIT(0);
        __syncthreads();

        #pragma unroll
        for (int i = 0; i < 4; i++) {
            float acc[4][4];
            #pragma unroll
            for (int j = 0; j < 4; j++)
                #pragma unroll
                for (int q = 0; q < 4; q++) acc[j][q] = 0.0f;

            #pragma unroll
            for (int ks = 0; ks < 4; ks++) {
                uint32_t aH[4], bf[2][4];
                ldsm4(aH, aFrag + i * (16 * 144) + ks * 32);
                #pragma unroll
                for (int j2 = 0; j2 < 2; j2++)
                    ldsm4(bf[j2], bFrag + j2 * (16 * 144) + ks * 32);
                #pragma unroll
                for (int j = 0; j < 4; j++)
                    mma16816(acc[j], aH[0], aH[1], aH[2], aH[3],
                             bf[j >> 1][2 * (j & 1)], bf[j >> 1][2 * (j & 1) + 1]);
            }
            #pragma unroll
            for (int j = 0; j < 4; j++) {
                cs[j][0] += exp2f(acc[j][0]) + exp2f(acc[j][2]);
                cs[j][1] += exp2f(acc[j][1]) + exp2f(acc[j][3]);
            }
        }

        __syncthreads();
        if (qt < 7) {
            #pragma unroll
            for (int p = 0; p < 4; p++) {
                const int idx = tid + p * 256;
                const int r = idx >> 3, c = idx & 7;
                const size_t go = ((size_t)(b * LL + (qt + 1) * 128 + r)) * DD + h * HDIM + c * 8;
                CP_ASYNC16(sb + CS_QH + r * 144 + c * 16, Qh + go);
            }
            CP_COMMIT();
        }
    }

    float* red = (float*)(sm + CS_RED);
    #pragma unroll
    for (int j = 0; j < 4; j++)
        #pragma unroll
        for (int hh = 0; hh < 2; hh++) {
            float v = cs[j][hh];
            v += __shfl_down_sync(0xffffffffu, v, 16);
            v += __shfl_down_sync(0xffffffffu, v, 8);
            v += __shfl_down_sync(0xffffffffu, v, 4);
            if (g == 0) red[wid * 32 + j * 8 + 2 * t + hh] = v;
        }
    __syncthreads();
    if (tid < 128) {
        const int col = tid;
        const int w2 = col >> 5, cl = col & 31;
        zinv[(size_t)bh * LL + kt * 128 + col] =
            1.0f / (red[w2 * 32 + cl] + red[(w2 + 4) * 32 + cl]);
    }
}

// ---------------------------------------------------------------------------
// HMMA AV (E = 1 + e): out = Sv + (1/1024) * sum_k e * (1024*Vp), e=exp2(S')-1
// 64-row q tiles, occupancy 2. Grid (16, 128), 256 thr.
// ---------------------------------------------------------------------------
#define AV_QH   0
#define AV_KH   9216
#define AV_E    27648
#define AV_VP0  45056
#define AV_VPB  17408
#define AV_SMEM 79872

__device__ __forceinline__ void av_load_kvp(
    uint32_t sb, int tid, int b, int h, int bh, int kt, int buf,
    const __half* __restrict__ Kh, const uint32_t* __restrict__ Vph)
{
    #pragma unroll
    for (int p = 0; p < 4; p++) {
        const int idx = tid + p * 256;
        const int r = idx >> 3, c = idx & 7;
        const size_t go = ((size_t)(b * LL + kt * 128 + r)) * DD + h * HDIM + c * 8;
        CP_ASYNC16(sb + AV_KH + r * 144 + c * 16, Kh + go);
    }
    const uint32_t vb = sb + AV_VP0 + buf * AV_VPB;
    #pragma unroll
    for (int p = 0; p < 4; p++) {
        const int idx = tid + p * 256;
        const int r = idx >> 4, c = idx & 15;
        const size_t go = ((size_t)bh * 512 + kt * 64 + r) * 64 + c * 4;
        CP_ASYNC16(vb + r * 272 + c * 16, Vph + go);
    }
}

__global__ __launch_bounds__(256, 2) void attn_av_tc(
    const __half* __restrict__ Qh, const __half* __restrict__ Kh,
    const uint32_t* __restrict__ Vph, const float* __restrict__ Sv,
    __half* __restrict__ Oh)
{
    extern __shared__ char sm[];
    const uint32_t sb = smem_u32(sm);
    const int tid = threadIdx.x;
    const int wid = tid >> 5;
    const int lane = tid & 31;
    const int g = lane >> 2;
    const int t = lane & 3;
    const int wm = wid >> 2;       // 0..1: 32-row slab
    const int wn = wid & 3;        // 0..3: 32-col (S) / 16-col (out) slab
    const int qt = blockIdx.x;     // 0..15, 64-row q tiles
    const int bh = blockIdx.y;
    const int b = bh >> 4, h = bh & 15;

    // ldmatrix bases
    const uint32_t aFragQ = sb + AV_QH
        + (wm * 32 + (lane & 15)) * 144 + (lane >> 4) * 16;
    const uint32_t bFragK = sb + AV_KH
        + (wn * 32 + ((lane >> 4) << 3) + (lane & 7)) * 144 + ((lane >> 3) & 1) * 16;
    const uint32_t eFrag = sb + AV_E
        + (wm * 32 + (lane & 15)) * 272 + (lane >> 4) * 16;

    // load Q tile 64x64 fp16 (512 chunks)
    #pragma unroll
    for (int p = 0; p < 2; p++) {
        const int idx = tid + p * 256;
        const int r = idx >> 3, c = idx & 7;
        const size_t go = ((size_t)(b * LL + qt * 64 + r)) * DD + h * HDIM + c * 8;
        CP_ASYNC16(sb + AV_QH + r * 144 + c * 16, Qh + go);
    }
    av_load_kvp(sb, tid, b, h, bh, 0, 0, Kh, Vph);
    CP_COMMIT();

    float out[2][2][4];
    #pragma unroll
    for (int i = 0; i < 2; i++)
        #pragma unroll
        for (int j = 0; j < 2; j++)
            #pragma unroll
            for (int q = 0; q < 4; q++) out[i][j][q] = 0.0f;

    for (int kt = 0; kt < 8; kt++) {
        const int buf = kt & 1;
        CP_WAIT(0);
        __syncthreads();

        // ---- GEMM1: S (64x128) = Q . K^T ----
        float acc[2][4][4];
        #pragma unroll
        for (int i = 0; i < 2; i++)
            #pragma unroll
            for (int j = 0; j < 4; j++)
                #pragma unroll
                for (int q = 0; q < 4; q++) acc[i][j][q] = 0.0f;

        #pragma unroll
        for (int ks = 0; ks < 4; ks++) {
            uint32_t aH[2][4], bf[2][4];
            #pragma unroll
            for (int i = 0; i < 2; i++)
                ldsm4(aH[i], aFragQ + i * (16 * 144) + ks * 32);
            #pragma unroll
            for (int j2 = 0; j2 < 2; j2++)
                ldsm4(bf[j2], bFragK + j2 * (16 * 144) + ks * 32);
            #pragma unroll
            for (int i = 0; i < 2; i++)
                #pragma unroll
                for (int j = 0; j < 4; j++)
                    mma16816(acc[i][j], aH[i][0], aH[i][1], aH[i][2], aH[i][3],
                             bf[j >> 1][2 * (j & 1)], bf[j >> 1][2 * (j & 1) + 1]);
        }

        // ---- e = exp2(S') - 1 -> smem (pitch 272) ----
        #pragma unroll
        for (int i = 0; i < 2; i++) {
            const int row = wm * 32 + i * 16 + g;
            #pragma unroll
            for (int j = 0; j < 4; j++) {
                const int colb = (wn * 32 + j * 8 + 2 * t) * 2;
                float e0 = exp2f(acc[i][j][0]) - 1.0f;
                float e1 = exp2f(acc[i][j][1]) - 1.0f;
                float e2 = exp2f(acc[i][j][2]) - 1.0f;
                float e3 = exp2f(acc[i][j][3]) - 1.0f;
                *(uint32_t*)(sm + AV_E + row * 272 + colb) = pack_h2(e0, e1);
                *(uint32_t*)(sm + AV_E + (row + 8) * 272 + colb) = pack_h2(e2, e3);
            }
        }
        __syncthreads();

        if (kt < 7) {
            av_load_kvp(sb, tid, b, h, bh, kt + 1, buf ^ 1, Kh, Vph);
            CP_COMMIT();
        }

        // ---- GEMM2: out (64x64) += e . Vp ----
        const char* VH = sm + AV_VP0 + buf * AV_VPB;
        #pragma unroll
        for (int ks = 0; ks < 8; ks++) {
            uint32_t aE[2][4], bV[2][2];
            #pragma unroll
            for (int i = 0; i < 2; i++)
                ldsm4(aE[i], eFrag + i * (16 * 272) + ks * 32);
            #pragma unroll
            for (int j = 0; j < 2; j++) {
                const int off = (ks * 8 + t) * 272 + (wn * 16 + j * 8 + g) * 4;
                bV[j][0] = *(const uint32_t*)(VH + off);
                bV[j][1] = *(const uint32_t*)(VH + off + 4 * 272);
            }
            #pragma unroll
            for (int i = 0; i < 2; i++)
                #pragma unroll
                for (int j = 0; j < 2; j++)
                    mma16816(out[i][j], aE[i][0], aE[i][1], aE[i][2], aE[i][3],
                             bV[j][0], bV[j][1]);
        }
        __syncthreads();
    }

    const float s = 1.0f / 1024.0f;
    #pragma unroll
    for (int i = 0; i < 2; i++) {
        const int row = qt * 64 + wm * 32 + i * 16 + g;
        #pragma unroll
        for (int j = 0; j < 2; j++) {
            const int dcol = wn * 16 + j * 8 + 2 * t;
            const float sv0 = Sv[(size_t)bh * HDIM + dcol];
            const float sv1 = Sv[(size_t)bh * HDIM + dcol + 1];
            const size_t o0 = ((size_t)b * LL + row) * DD + h * HDIM + dcol;
            const size_t o1 = ((size_t)b * LL + row + 8) * DD + h * HDIM + dcol;
            *(uint32_t*)(Oh + o0) =
                pack_h2(out[i][j][0] * s + sv0, out[i][j][1] * s + sv1);
            *(uint32_t*)(Oh + o1) =
                pack_h2(out[i][j][2] * s + sv0, out[i][j][3] * s + sv1);
        }
    }
}

// ---------------------------------------------------------------------------
// Launch
// ---------------------------------------------------------------------------
extern "C" void kernel_launch(void* const* d_in, const int* in_sizes, int n_in,
                              void* d_out, int out_size)
{
    (void)in_sizes; (void)n_in; (void)out_size;

    const float* x_q = (const float*)d_in[0];
    const float* x_k = (const float*)d_in[1];
    const float* x_v = (const float*)d_in[2];
    // d_in[3] = mask: unused (reference never applies it)
    const float* Wq  = (const float*)d_in[4];
    const float* bq  = (const float*)d_in[5];
    const float* Wk  = (const float*)d_in[6];
    const float* bk  = (const float*)d_in[7];
    const float* Wv  = (const float*)d_in[8];
    const float* bv  = (const float*)d_in[9];
    const float* Wo  = (const float*)d_in[10];
    const float* bo  = (const float*)d_in[11];

    float *pZi, *pSz, *pSx, *pSv;
    __half *pAh, *pXk, *pXv, *pQh, *pKh;
    uint32_t *pWp, *pVh;
    cudaGetSymbolAddress((void**)&pZi, g_zinv);
    cudaGetSymbolAddress((void**)&pSz, g_sz);
    cudaGetSymbolAddress((void**)&pSx, g_sx);
    cudaGetSymbolAddress((void**)&pSv, g_Sv);
    cudaGetSymbolAddress((void**)&pAh, g_Ah);
    cudaGetSymbolAddress((void**)&pXk, g_Xk);
    cudaGetSymbolAddress((void**)&pXv, g_Xv);
    cudaGetSymbolAddress((void**)&pWp, g_Wp);
    cudaGetSymbolAddress((void**)&pQh, g_Qh);
    cudaGetSymbolAddress((void**)&pKh, g_Kh);
    cudaGetSymbolAddress((void**)&pVh, g_Vph);

    cudaFuncSetAttribute(tc_gemm_1p_kernel,
                         cudaFuncAttributeMaxDynamicSharedMemorySize, F_SMEM);
    cudaFuncSetAttribute(attn_colsum_tc,
                         cudaFuncAttributeMaxDynamicSharedMemorySize, CS_SMEM);
    cudaFuncSetAttribute(attn_av_tc,
                         cudaFuncAttributeMaxDynamicSharedMemorySize, AV_SMEM);
    cudaFuncSetAttribute(sx_kernel,
                         cudaFuncAttributeMaxDynamicSharedMemorySize, 65536);

    const int n4 = MTOT * DD / 4;
    const dim3 t256(256);
    const int npack = (DD / 2) * DD;
    const dim3 gGemm(DD / 128, MTOT / 128, 1);
    const dim3 gGemmQK(DD / 128, MTOT / 128, 2);

    // All fp32->fp16 conversions and W packs, batched
    tof16_batch<<<dim3((n4 + 255) / 256, 3), t256>>>(
        x_q, x_k, x_v, pAh, pXk, pXv, n4);
    pack_w_batch<<<dim3((npack + 255) / 256, 4), t256>>>(Wq, Wk, Wv, Wo, pWp);

    // Q + K projections in one launch (z=0: Q scaled log2e/32; z=1: K)
    tc_gemm_1p_kernel<<<gGemmQK, 256, F_SMEM>>>(
        pAh, pWp, bq, nullptr, pQh, nullptr, nullptr, SCALE_Q, 1,
        pXk, bk, pKh, 1.0f);

    // zinv = 1 / column-softmax sums (needs only Qh, Kh)
    attn_colsum_tc<<<dim3(8, BB * HH), 256, CS_SMEM>>>(pQh, pKh, pZi);

    // Exact Sv via commuted identity: Sv = (sum_k x_v zi) @ Wv + bv * sum(zi)
    sumz_kernel<<<BB * HH, 256>>>(pZi, pSz);
    sx_kernel<<<dim3(BB, 16), 256, 65536>>>(x_v, pZi, pSx);
    sv_kernel<<<BB * HH, 256>>>(pSx, Wv, bv, pSz, pSv);

    // V projection fused with Vp pack (mode 2): writes 1024*V/Z k-pairs
    tc_gemm_1p_kernel<<<gGemm, 256, F_SMEM>>>(
        pXv, pWp + 2 * WPS, bv, nullptr, nullptr, pZi, pVh, 1.0f, 2,
        nullptr, nullptr, nullptr, 0.0f);

    // AV -> fp16 attention output in g_Ah
    attn_av_tc<<<dim3(16, BB * HH), 256, AV_SMEM>>>(pQh, pKh, pVh, pSv, pAh);

    // Output projection (mode 0) -> d_out
    tc_gemm_1p_kernel<<<gGemm, 256, F_SMEM>>>(
        pAh, pWp + 3 * WPS, bo, (float*)d_out, nullptr, nullptr, nullptr, 1.0f, 0,
        nullptr, nullptr, nullptr, 0.0f);
}

// round 16
// speedup vs baseline: 1.0790x; 1.0108x over previous
#include <cuda_runtime.h>
#include <cuda_fp16.h>
#include <cstdint>
#include <math.h>

// Problem constants
#define BB   8
#define LL   1024
#define DD   1024
#define HH   16
#define HDIM 64
#define MTOT (BB*LL)
#define WPS  ((size_t)(DD/2) * DD)
#define SCALE_Q (0.03125f * 1.44269504088896340736f)   // (1/sqrt(D)) * log2(e)

// ---------------------------------------------------------------------------
// Scratch (device globals)
// ---------------------------------------------------------------------------
__device__ float g_zinv[(size_t)BB * HH * LL];      // 512 KB (1/Z)
__device__ float g_sz[(size_t)BB * HH];             // sum_k zinv
__device__ float g_sx[(size_t)BB * HH * DD];        // 512 KB (sum_k x_v * zinv)
__device__ float g_Sv[(size_t)BB * HH * HDIM];      // 32 KB  (exact sum_k V/Z)
__device__ __half g_Ah[(size_t)MTOT * DD];          // 16 MB (x_q fp16 / attn out)
__device__ __half g_Xk[(size_t)MTOT * DD];          // 16 MB (x_k fp16)
__device__ __half g_Xv[(size_t)MTOT * DD];          // 16 MB (x_v fp16)
__device__ uint32_t g_Wp[(size_t)4 * (DD/2) * DD];  // 8 MB (4 W's k-pair fp16x2)
__device__ __half g_Qh[(size_t)MTOT * DD];          // 16 MB (Q*log2e/32, fp16)
__device__ __half g_Kh[(size_t)MTOT * DD];          // 16 MB
__device__ uint32_t g_Vph[(size_t)BB * HH * (LL/2) * HDIM];  // 16 MB (1024*V/Z k-pair)

// ---------------------------------------------------------------------------
// Helpers
// ---------------------------------------------------------------------------
__device__ __forceinline__ void mma16816(float c[4],
    uint32_t a0, uint32_t a1, uint32_t a2, uint32_t a3,
    uint32_t b0, uint32_t b1)
{
    asm volatile(
        "mma.sync.aligned.m16n8k16.row.col.f32.f16.f16.f32 "
        "{%0,%1,%2,%3}, {%4,%5,%6,%7}, {%8,%9}, {%0,%1,%2,%3};"
        : "+f"(c[0]), "+f"(c[1]), "+f"(c[2]), "+f"(c[3])
        : "r"(a0), "r"(a1), "r"(a2), "r"(a3), "r"(b0), "r"(b1));
}

__device__ __forceinline__ void ldsm4(uint32_t r[4], uint32_t addr)
{
    asm volatile(
        "ldmatrix.sync.aligned.m8n8.x4.shared.b16 {%0,%1,%2,%3}, [%4];"
        : "=r"(r[0]), "=r"(r[1]), "=r"(r[2]), "=r"(r[3]) : "r"(addr));
}

__device__ __forceinline__ uint32_t smem_u32(const void* p) {
    uint32_t a;
    asm("{ .reg .u64 t; cvta.to.shared.u64 t, %1; cvt.u32.u64 %0, t; }"
        : "=r"(a) : "l"(p));
    return a;
}

#define CP_ASYNC16(dst_u32, src_ptr) \
    asm volatile("cp.async.cg.shared.global [%0], [%1], 16;" \
        :: "r"(dst_u32), "l"(src_ptr) : "memory")
#define CP_COMMIT() asm volatile("cp.async.commit_group;" ::: "memory")
#define CP_WAIT(n)  asm volatile("cp.async.wait_group %0;" :: "n"(n) : "memory")

__device__ __forceinline__ uint32_t pack_h2(float x, float y) {
    __half2 p = __floats2half2_rn(x, y);   // .x = x (low half)
    return *(uint32_t*)&p;
}

// ---------------------------------------------------------------------------
// fp32 -> fp16, batched over 3 inputs (blockIdx.y selects)
// ---------------------------------------------------------------------------
__global__ __launch_bounds__(256) void tof16_batch(
    const float* __restrict__ x0, const float* __restrict__ x1,
    const float* __restrict__ x2,
    __half* __restrict__ h0, __half* __restrict__ h1, __half* __restrict__ h2,
    int n4)
{
    int i = blockIdx.x * blockDim.x + threadIdx.x;
    if (i >= n4) return;
    const float* x;
    __half* h;
    if (blockIdx.y == 0)      { x = x0; h = h0; }
    else if (blockIdx.y == 1) { x = x1; h = h1; }
    else                      { x = x2; h = h2; }
    float4 v = ((const float4*)x)[i];
    __half2* hp = (__half2*)h;
    hp[2*i]   = __floats2half2_rn(v.x, v.y);
    hp[2*i+1] = __floats2half2_rn(v.z, v.w);
}

// ---------------------------------------------------------------------------
// pack 4 W's [K,N] fp32 -> k-pair fp16x2 [k2][n] (blockIdx.y selects)
// ---------------------------------------------------------------------------
__global__ __launch_bounds__(256) void pack_w_batch(
    const float* __restrict__ W0, const float* __restrict__ W1,
    const float* __restrict__ W2, const float* __restrict__ W3,
    uint32_t* __restrict__ P)
{
    int i = blockIdx.x * blockDim.x + threadIdx.x;
    if (i >= (DD/2) * DD) return;
    const float* W;
    if (blockIdx.y == 0)      W = W0;
    else if (blockIdx.y == 1) W = W1;
    else if (blockIdx.y == 2) W = W2;
    else                      W = W3;
    uint32_t* Ph = P + (size_t)blockIdx.y * WPS;
    int k2 = i >> 10, n = i & (DD - 1);
    Ph[i] = pack_h2(W[(size_t)(2*k2) * DD + n], W[(size_t)(2*k2 + 1) * DD + n]);
}

// ---------------------------------------------------------------------------
// sz[bh] = sum_k zinv[bh,k]
// ---------------------------------------------------------------------------
__global__ __launch_bounds__(256) void sumz_kernel(
    const float* __restrict__ Zi, float* __restrict__ Sz)
{
    __shared__ float red[256];
    const int bh = blockIdx.x;
    const int tid = threadIdx.x;
    float s = 0.0f;
    #pragma unroll
    for (int p = 0; p < 4; p++) s += Zi[(size_t)bh * LL + tid + p * 256];
    red[tid] = s;
    __syncthreads();
    for (int w = 128; w > 0; w >>= 1) {
        if (tid < w) red[tid] += red[tid + w];
        __syncthreads();
    }
    if (tid == 0) Sz[bh] = red[0];
}

// ---------------------------------------------------------------------------
// s_x[bh][d'] = sum_k x_v[b,k,d'] * zinv[bh,k]   (exact fp32)
// ---------------------------------------------------------------------------
__global__ __launch_bounds__(256) void sx_kernel(
    const float* __restrict__ xv, const float* __restrict__ Zi,
    float* __restrict__ Sx)
{
    extern __shared__ float szi[];   // [16][1024]
    const int b = blockIdx.x;
    const int dc = blockIdx.y;       // 0..15
    const int tid = threadIdx.x;
    const int d = tid & 63;
    const int s = tid >> 6;          // k-slice 0..3

    for (int i = tid; i < 16 * 1024; i += 256)
        szi[i] = Zi[(size_t)(b * 16) * LL + i];
    __syncthreads();

    float acc[16];
    #pragma unroll
    for (int h = 0; h < 16; h++) acc[h] = 0.0f;

    const int dglob = dc * 64 + d;
    const int k0 = s * 256;
    for (int k = k0; k < k0 + 256; k++) {
        float x = xv[((size_t)b * LL + k) * DD + dglob];
        #pragma unroll
        for (int h = 0; h < 16; h++)
            acc[h] = fmaf(x, szi[h * 1024 + k], acc[h]);
    }
    __syncthreads();
    float* red = szi;   // [4][16][64]
    #pragma unroll
    for (int h = 0; h < 16; h++)
        red[(s * 16 + h) * 64 + d] = acc[h];
    __syncthreads();
    for (int i = tid; i < 16 * 64; i += 256) {
        int h = i >> 6, dd = i & 63;
        float v = red[(0 * 16 + h) * 64 + dd] + red[(1 * 16 + h) * 64 + dd]
                + red[(2 * 16 + h) * 64 + dd] + red[(3 * 16 + h) * 64 + dd];
        Sx[(size_t)(b * 16 + h) * DD + dc * 64 + dd] = v;
    }
}

// ---------------------------------------------------------------------------
// Sv[bh][d] = sum_{d'} s_x[bh][d'] * Wv[d'][h*64+d] + bv[h*64+d]*sz[bh]
// ---------------------------------------------------------------------------
__global__ __launch_bounds__(256) void sv_kernel(
    const float* __restrict__ Sx, const float* __restrict__ Wv,
    const float* __restrict__ bv, const float* __restrict__ Sz,
    float* __restrict__ Sv)
{
    __shared__ float sxr[1024];
    __shared__ float red[4 * 64];
    const int bh = blockIdx.x;
    const int h = bh & 15;
    const int tid = threadIdx.x;
    const int d = tid & 63;
    const int s = tid >> 6;

    for (int i = tid; i < 1024; i += 256)
        sxr[i] = Sx[(size_t)bh * DD + i];
    __syncthreads();

    float acc = 0.0f;
    const int k0 = s * 256;
    const int col = h * HDIM + d;
    for (int k = k0; k < k0 + 256; k++)
        acc = fmaf(sxr[k], Wv[(size_t)k * DD + col], acc);
    red[s * 64 + d] = acc;
    __syncthreads();
    if (tid < 64)
        Sv[(size_t)bh * HDIM + d] =
            red[d] + red[64 + d] + red[128 + d] + red[192 + d] + bv[col] * Sz[bh];
}

// ---------------------------------------------------------------------------
// Single-pass fp16 HMMA GEMM (128-col tile, ldmatrix A streamed per i-block).
// mode 0: fp32 C = A@W + bias
// mode 1: fp16 Hout = (A@W + bias) * oscale  (gridDim.z may be 2: second set)
// mode 2: Vp pack: Vout[bh][k2][d] = fp16x2{ 1024*zi*(A@W+bias) } k-pairs
// SMEM per buffer: A 18432 + B 16896 = 35328; x2 = 70656 -> 2 CTAs/SM.
// ---------------------------------------------------------------------------
#define F_AH   0
#define F_BH   18432
#define F_BUF  35328
#define F_SMEM (2 * F_BUF)

__device__ __forceinline__ void gemm1p_load(
    uint32_t sb0, int buf, int tid, int m0, int n0, int kt,
    const __half* __restrict__ Ah, const uint32_t* __restrict__ Bh)
{
    const uint32_t sb = sb0 + buf * F_BUF;
    #pragma unroll
    for (int p = 0; p < 4; p++) {
        const int idx = tid + p * 256;
        const int r = idx >> 3, c = idx & 7;
        const size_t g = (size_t)(m0 + r) * DD + kt * 64 + c * 8;
        CP_ASYNC16(sb + F_AH + r * 144 + c * 16, Ah + g);
    }
    #pragma unroll
    for (int p = 0; p < 4; p++) {
        const int idx = tid + p * 256;
        const int r = idx >> 5, c = idx & 31;
        const size_t g = (size_t)(kt * 32 + r) * DD + n0 + c * 4;
        CP_ASYNC16(sb + F_BH + r * 528 + c * 16, Bh + g);
    }
}

__global__ __launch_bounds__(256, 2) void tc_gemm_1p_kernel(
    const __half* __restrict__ Ah_, const uint32_t* __restrict__ Bh_,
    const float* __restrict__ bias_, float* __restrict__ C,
    __half* __restrict__ Hout_, const float* __restrict__ Zi,
    uint32_t* __restrict__ Vout, float oscale_, int mode,
    const __half* __restrict__ Ah2, const float* __restrict__ bias2,
    __half* __restrict__ Hout2, float oscale2)
{
    const __half* Ah = Ah_;
    const uint32_t* Bh = Bh_;
    const float* bias = bias_;
    __half* Hout = Hout_;
    float oscale = oscale_;
    if (blockIdx.z == 1) {
        Ah = Ah2; Bh = Bh_ + WPS; bias = bias2; Hout = Hout2; oscale = oscale2;
    }

    extern __shared__ char sm[];
    const uint32_t smem_base = smem_u32(sm);
    const int tid = threadIdx.x;
    const int wid = tid >> 5;
    const int lane = tid & 31;
    const int g = lane >> 2;
    const int t = lane & 3;
    const int wm = wid >> 2;
    const int wn = wid & 3;
    const int n0 = blockIdx.x * 128;
    const int m0 = blockIdx.y * 128;

    // per-lane ldmatrix base for A fragments
    const uint32_t aFrag = smem_base + F_AH
        + (wm * 64 + (lane & 15)) * 144 + (lane >> 4) * 16;

    float c[4][4][4];
    #pragma unroll
    for (int i = 0; i < 4; i++)
        #pragma unroll
        for (int j = 0; j < 4; j++)
            #pragma unroll
            for (int q = 0; q < 4; q++) c[i][j][q] = 0.0f;

    gemm1p_load(smem_base, 0, tid, m0, n0, 0, Ah, Bh);
    CP_COMMIT();

    for (int kt = 0; kt < 16; kt++) {
        const int buf = kt & 1;
        if (kt < 15) {
            gemm1p_load(smem_base, buf ^ 1, tid, m0, n0, kt + 1, Ah, Bh);
            CP_COMMIT();
            CP_WAIT(1);
        } else {
            CP_WAIT(0);
        }
        __syncthreads();

        const uint32_t aB = aFrag + buf * F_BUF;
        const char* Bb = sm + buf * F_BUF + F_BH;

        #pragma unroll
        for (int ks = 0; ks < 4; ks++) {
            uint32_t bH[4][2];
            #pragma unroll
            for (int j = 0; j < 4; j++) {
                const int off = (ks * 8 + t) * 528 + (wn * 32 + j * 8 + g) * 4;
                bH[j][0] = *(const uint32_t*)(Bb + off);
                bH[j][1] = *(const uint32_t*)(Bb + off + 4 * 528);
            }
            // stream A fragments: one ldsm4 (4 regs) per i-block
            #pragma unroll
            for (int i = 0; i < 4; i++) {
                uint32_t aH[4];
                ldsm4(aH, aB + i * (16 * 144) + ks * 32);
                #pragma unroll
                for (int j = 0; j < 4; j++)
                    mma16816(c[i][j], aH[0], aH[1], aH[2], aH[3],
                             bH[j][0], bH[j][1]);
            }
        }
        __syncthreads();
    }

    if (mode == 2) {
        // Stage fp32 (C + bias) tile in smem, then repack as zinv-scaled
        // fp16 k-pairs into Vp layout. stage pitch = 132 floats (528 B).
        float* stage = (float*)sm;                 // 128 x 132 fp32 = 67584 B
        float* ziS   = (float*)(sm + 67584);       // [2][128] fp32
        #pragma unroll
        for (int j = 0; j < 4; j++) {
            const int cl = wn * 32 + j * 8 + 2 * t;
            const float2 bv = *(const float2*)(bias + n0 + cl);
            #pragma unroll
            for (int i = 0; i < 4; i++) {
                const int rl = wm * 64 + i * 16 + g;
                stage[rl * 132 + cl]       = c[i][j][0] + bv.x;
                stage[rl * 132 + cl + 1]   = c[i][j][1] + bv.y;
                stage[(rl + 8) * 132 + cl]     = c[i][j][2] + bv.x;
                stage[(rl + 8) * 132 + cl + 1] = c[i][j][3] + bv.y;
            }
        }
        const int b = m0 >> 10;
        const int l0 = m0 & 1023;
        const int h0 = n0 >> 6;        // first of 2 heads in this col block
        {
            const int hh = tid >> 7, l = tid & 127;
            ziS[tid] = Zi[(size_t)(b * 16 + h0 + hh) * LL + l0 + l] * 1024.0f;
        }
        __syncthreads();
        const int k20 = l0 >> 1;
        #pragma unroll
        for (int p = 0; p < 32; p++) {
            const int i = tid + p * 256;          // 0..8191
            const int hh = i >> 12;
            const int k2r = (i >> 6) & 63;
            const int d = i & 63;
            float v0 = stage[(2 * k2r) * 132 + hh * 64 + d] * ziS[hh * 128 + 2 * k2r];
            float v1 = stage[(2 * k2r + 1) * 132 + hh * 64 + d] * ziS[hh * 128 + 2 * k2r + 1];
            Vout[((size_t)(b * 16 + h0 + hh) * 512 + k20 + k2r) * 64 + d] =
                pack_h2(v0, v1);
        }
        return;
    }

    #pragma unroll
    for (int j = 0; j < 4; j++) {
        const int col = n0 + wn * 32 + j * 8 + 2 * t;
        const float2 bv = *(const float2*)(bias + col);
        #pragma unroll
        for (int i = 0; i < 4; i++) {
            const int row = m0 + wm * 64 + i * 16 + g;
            float v0 = c[i][j][0] + bv.x, v1 = c[i][j][1] + bv.y;
            float v2 = c[i][j][2] + bv.x, v3 = c[i][j][3] + bv.y;
            if (mode == 0) {
                float* o = C + (size_t)row * DD + col;
                *(float2*)o = make_float2(v0, v1);
                *(float2*)(o + 8 * DD) = make_float2(v2, v3);
            } else {
                *(uint32_t*)(Hout + (size_t)row * DD + col) =
                    pack_h2(v0 * oscale, v1 * oscale);
                *(uint32_t*)(Hout + (size_t)(row + 8) * DD + col) =
                    pack_h2(v2 * oscale, v3 * oscale);
            }
        }
    }
}

// ---------------------------------------------------------------------------
// HMMA colsum (fp16, ldmatrix, register-lean): zinv = 1/sum_q exp2(S')
// acc reused across the 4 row-blocks -> 3 CTAs/SM. (measured-best form)
// ---------------------------------------------------------------------------
#define CS_KH  0
#define CS_QH  18432
#define CS_RED 36864
#define CS_SMEM 37888

__global__ __launch_bounds__(256, 3) void attn_colsum_tc(
    const __half* __restrict__ Qh, const __half* __restrict__ Kh,
    float* __restrict__ zinv)
{
    extern __shared__ char sm[];
    const uint32_t sb = smem_u32(sm);
    const int tid = threadIdx.x;
    const int wid = tid >> 5;
    const int lane = tid & 31;
    const int g = lane >> 2;
    const int t = lane & 3;
    const int wm = wid >> 2;
    const int wn = wid & 3;
    const int kt = blockIdx.x;
    const int bh = blockIdx.y;
    const int b = bh >> 4, h = bh & 15;

    // ldmatrix bases
    const uint32_t aFrag = sb + CS_QH
        + (wm * 64 + (lane & 15)) * 144 + (lane >> 4) * 16;
    const uint32_t bFrag = sb + CS_KH
        + (wn * 32 + ((lane >> 4) << 3) + (lane & 7)) * 144 + ((lane >> 3) & 1) * 16;

    #pragma unroll
    for (int p = 0; p < 4; p++) {
        const int idx = tid + p * 256;
        const int r = idx >> 3, c = idx & 7;
        const size_t go = ((size_t)(b * LL + kt * 128 + r)) * DD + h * HDIM + c * 8;
        CP_ASYNC16(sb + CS_KH + r * 144 + c * 16, Kh + go);
    }
    #pragma unroll
    for (int p = 0; p < 4; p++) {
        const int idx = tid + p * 256;
        const int r = idx >> 3, c = idx & 7;
        const size_t go = ((size_t)(b * LL + r)) * DD + h * HDIM + c * 8;
        CP_ASYNC16(sb + CS_QH + r * 144 + c * 16, Qh + go);
    }
    CP_COMMIT();

    float cs[4][2];
    #pragma unroll
    for (int j = 0; j < 4; j++) { cs[j][0] = 0.0f; cs[j][1] = 0.0f; }

    for (int qt = 0; qt < 8; qt++) {
        CP_WAIT(0);
        __syncthreads();

        #pragma unroll
        for (int i = 0; i < 4; i++) {
            float acc[4][4];
            #pragma unroll
            for (int j = 0; j < 4; j++)
                #pragma unroll
                for (int q = 0; q < 4; q++) acc[j][q] = 0.0f;

            #pragma unroll
            for (int ks = 0; ks < 4; ks++) {
                uint32_t aH[4], bf[2][4];
                ldsm4(aH, aFrag + i * (16 * 144) + ks * 32);
                #pragma unroll
                for (int j2 = 0; j2 < 2; j2++)
                    ldsm4(bf[j2], bFrag + j2 * (16 * 144) + ks * 32);
                #pragma unroll
                for (int j = 0; j < 4; j++)
                    mma16816(acc[j], aH[0], aH[1], aH[2], aH[3],
                             bf[j >> 1][2 * (j & 1)], bf[j >> 1][2 * (j & 1) + 1]);
            }
            #pragma unroll
            for (int j = 0; j < 4; j++) {
                cs[j][0] += exp2f(acc[j][0]) + exp2f(acc[j][2]);
                cs[j][1] += exp2f(acc[j][1]) + exp2f(acc[j][3]);
            }
        }

        __syncthreads();
        if (qt < 7) {
            #pragma unroll
            for (int p = 0; p < 4; p++) {
                const int idx = tid + p * 256;
                const int r = idx >> 3, c = idx & 7;
                const size_t go = ((size_t)(b * LL + (qt + 1) * 128 + r)) * DD + h * HDIM + c * 8;
                CP_ASYNC16(sb + CS_QH + r * 144 + c * 16, Qh + go);
            }
            CP_COMMIT();
        }
    }

    float* red = (float*)(sm + CS_RED);
    #pragma unroll
    for (int j = 0; j < 4; j++)
        #pragma unroll
        for (int hh = 0; hh < 2; hh++) {
            float v = cs[j][hh];
            v += __shfl_down_sync(0xffffffffu, v, 16);
            v += __shfl_down_sync(0xffffffffu, v, 8);
            v += __shfl_down_sync(0xffffffffu, v, 4);
            if (g == 0) red[wid * 32 + j * 8 + 2 * t + hh] = v;
        }
    __syncthreads();
    if (tid < 128) {
        const int col = tid;
        const int w2 = col >> 5, cl = col & 31;
        zinv[(size_t)bh * LL + kt * 128 + col] =
            1.0f / (red[w2 * 32 + cl] + red[(w2 + 4) * 32 + cl]);
    }
}

// ---------------------------------------------------------------------------
// HMMA AV (E = 1 + e): out = Sv + (1/1024) * sum_k e * (1024*Vp), e=exp2(S')-1
// 64-row q tiles, single-buffered Vp, occupancy 3. Grid (16, 128), 256 thr.
// SMEM: QH 9216 | KH 18432 | E 17408 | VP 17408 = 62464 (x3 = 187KB)
// ---------------------------------------------------------------------------
#define AV_QH   0
#define AV_KH   9216
#define AV_E    27648
#define AV_VP   45056
#define AV_SMEM 62464

__device__ __forceinline__ void av_load_k(
    uint32_t sb, int tid, int b, int h, int kt,
    const __half* __restrict__ Kh)
{
    #pragma unroll
    for (int p = 0; p < 4; p++) {
        const int idx = tid + p * 256;
        const int r = idx >> 3, c = idx & 7;
        const size_t go = ((size_t)(b * LL + kt * 128 + r)) * DD + h * HDIM + c * 8;
        CP_ASYNC16(sb + AV_KH + r * 144 + c * 16, Kh + go);
    }
}

__device__ __forceinline__ void av_load_vp(
    uint32_t sb, int tid, int bh, int kt,
    const uint32_t* __restrict__ Vph)
{
    #pragma unroll
    for (int p = 0; p < 4; p++) {
        const int idx = tid + p * 256;
        const int r = idx >> 4, c = idx & 15;
        const size_t go = ((size_t)bh * 512 + kt * 64 + r) * 64 + c * 4;
        CP_ASYNC16(sb + AV_VP + r * 272 + c * 16, Vph + go);
    }
}

__global__ __launch_bounds__(256, 3) void attn_av_tc(
    const __half* __restrict__ Qh, const __half* __restrict__ Kh,
    const uint32_t* __restrict__ Vph, const float* __restrict__ Sv,
    __half* __restrict__ Oh)
{
    extern __shared__ char sm[];
    const uint32_t sb = smem_u32(sm);
    const int tid = threadIdx.x;
    const int wid = tid >> 5;
    const int lane = tid & 31;
    const int g = lane >> 2;
    const int t = lane & 3;
    const int wm = wid >> 2;       // 0..1: 32-row slab
    const int wn = wid & 3;        // 0..3: 32-col (S) / 16-col (out) slab
    const int qt = blockIdx.x;     // 0..15, 64-row q tiles
    const int bh = blockIdx.y;
    const int b = bh >> 4, h = bh & 15;

    // ldmatrix bases
    const uint32_t aFragQ = sb + AV_QH
        + (wm * 32 + (lane & 15)) * 144 + (lane >> 4) * 16;
    const uint32_t bFragK = sb + AV_KH
        + (wn * 32 + ((lane >> 4) << 3) + (lane & 7)) * 144 + ((lane >> 3) & 1) * 16;
    const uint32_t eFrag = sb + AV_E
        + (wm * 32 + (lane & 15)) * 272 + (lane >> 4) * 16;

    // load Q tile 64x64 fp16 (512 chunks)
    #pragma unroll
    for (int p = 0; p < 2; p++) {
        const int idx = tid + p * 256;
        const int r = idx >> 3, c = idx & 7;
        const size_t go = ((size_t)(b * LL + qt * 64 + r)) * DD + h * HDIM + c * 8;
        CP_ASYNC16(sb + AV_QH + r * 144 + c * 16, Qh + go);
    }
    av_load_k(sb, tid, b, h, 0, Kh);
    av_load_vp(sb, tid, bh, 0, Vph);
    CP_COMMIT();

    float out[2][2][4];
    #pragma unroll
    for (int i = 0; i < 2; i++)
        #pragma unroll
        for (int j = 0; j < 2; j++)
            #pragma unroll
            for (int q = 0; q < 4; q++) out[i][j][q] = 0.0f;

    for (int kt = 0; kt < 8; kt++) {
        CP_WAIT(0);
        __syncthreads();

        // ---- GEMM1: S (64x128) = Q . K^T (A streamed per i) ----
        float acc[2][4][4];
        #pragma unroll
        for (int i = 0; i < 2; i++)
            #pragma unroll
            for (int j = 0; j < 4; j++)
                #pragma unroll
                for (int q = 0; q < 4; q++) acc[i][j][q] = 0.0f;

        #pragma unroll
        for (int ks = 0; ks < 4; ks++) {
            uint32_t bf[2][4];
            #pragma unroll
            for (int j2 = 0; j2 < 2; j2++)
                ldsm4(bf[j2], bFragK + j2 * (16 * 144) + ks * 32);
            #pragma unroll
            for (int i = 0; i < 2; i++) {
                uint32_t aH[4];
                ldsm4(aH, aFragQ + i * (16 * 144) + ks * 32);
                #pragma unroll
                for (int j = 0; j < 4; j++)
                    mma16816(acc[i][j], aH[0], aH[1], aH[2], aH[3],
                             bf[j >> 1][2 * (j & 1)], bf[j >> 1][2 * (j & 1) + 1]);
            }
        }

        // ---- e = exp2(S') - 1 -> smem (pitch 272) ----
        #pragma unroll
        for (int i = 0; i < 2; i++) {
            const int row = wm * 32 + i * 16 + g;
            #pragma unroll
            for (int j = 0; j < 4; j++) {
                const int colb = (wn * 32 + j * 8 + 2 * t) * 2;
                float e0 = exp2f(acc[i][j][0]) - 1.0f;
                float e1 = exp2f(acc[i][j][1]) - 1.0f;
                float e2 = exp2f(acc[i][j][2]) - 1.0f;
                float e3 = exp2f(acc[i][j][3]) - 1.0f;
                *(uint32_t*)(sm + AV_E + row * 272 + colb) = pack_h2(e0, e1);
                *(uint32_t*)(sm + AV_E + (row + 8) * 272 + colb) = pack_h2(e2, e3);
            }
        }
        __syncthreads();   // E visible; all GEMM1 reads of KH done

        if (kt < 7) {
            av_load_k(sb, tid, b, h, kt + 1, Kh);   // overlaps GEMM2
            CP_COMMIT();
        }

        // ---- GEMM2: out (64x64) += e . Vp ----
        #pragma unroll
        for (int ks = 0; ks < 8; ks++) {
            uint32_t aE[2][4], bV[2][2];
            #pragma unroll
            for (int i = 0; i < 2; i++)
                ldsm4(aE[i], eFrag + i * (16 * 272) + ks * 32);
            #pragma unroll
            for (int j = 0; j < 2; j++) {
                const int off = AV_VP + (ks * 8 + t) * 272 + (wn * 16 + j * 8 + g) * 4;
                bV[j][0] = *(const uint32_t*)(sm + off);
                bV[j][1] = *(const uint32_t*)(sm + off + 4 * 272);
            }
            #pragma unroll
            for (int i = 0; i < 2; i++)
                #pragma unroll
                for (int j = 0; j < 2; j++)
                    mma16816(out[i][j], aE[i][0], aE[i][1], aE[i][2], aE[i][3],
                             bV[j][0], bV[j][1]);
        }
        __syncthreads();   // all reads of VP done before overwrite

        if (kt < 7) {
            av_load_vp(sb, tid, bh, kt + 1, Vph);   // hides under next GEMM1+exp
            CP_COMMIT();
        }
    }

    const float s = 1.0f / 1024.0f;
    #pragma unroll
    for (int i = 0; i < 2; i++) {
        const int row = qt * 64 + wm * 32 + i * 16 + g;
        #pragma unroll
        for (int j = 0; j < 2; j++) {
            const int dcol = wn * 16 + j * 8 + 2 * t;
            const float sv0 = Sv[(size_t)bh * HDIM + dcol];
            const float sv1 = Sv[(size_t)bh * HDIM + dcol + 1];
            const size_t o0 = ((size_t)b * LL + row) * DD + h * HDIM + dcol;
            const size_t o1 = ((size_t)b * LL + row + 8) * DD + h * HDIM + dcol;
            *(uint32_t*)(Oh + o0) =
                pack_h2(out[i][j][0] * s + sv0, out[i][j][1] * s + sv1);
            *(uint32_t*)(Oh + o1) =
                pack_h2(out[i][j][2] * s + sv0, out[i][j][3] * s + sv1);
        }
    }
}

// ---------------------------------------------------------------------------
// Launch
// ---------------------------------------------------------------------------
extern "C" void kernel_launch(void* const* d_in, const int* in_sizes, int n_in,
                              void* d_out, int out_size)
{
    (void)in_sizes; (void)n_in; (void)out_size;

    const float* x_q = (const float*)d_in[0];
    const float* x_k = (const float*)d_in[1];
    const float* x_v = (const float*)d_in[2];
    // d_in[3] = mask: unused (reference never applies it)
    const float* Wq  = (const float*)d_in[4];
    const float* bq  = (const float*)d_in[5];
    const float* Wk  = (const float*)d_in[6];
    const float* bk  = (const float*)d_in[7];
    const float* Wv  = (const float*)d_in[8];
    const float* bv  = (const float*)d_in[9];
    const float* Wo  = (const float*)d_in[10];
    const float* bo  = (const float*)d_in[11];

    float *pZi, *pSz, *pSx, *pSv;
    __half *pAh, *pXk, *pXv, *pQh, *pKh;
    uint32_t *pWp, *pVh;
    cudaGetSymbolAddress((void**)&pZi, g_zinv);
    cudaGetSymbolAddress((void**)&pSz, g_sz);
    cudaGetSymbolAddress((void**)&pSx, g_sx);
    cudaGetSymbolAddress((void**)&pSv, g_Sv);
    cudaGetSymbolAddress((void**)&pAh, g_Ah);
    cudaGetSymbolAddress((void**)&pXk, g_Xk);
    cudaGetSymbolAddress((void**)&pXv, g_Xv);
    cudaGetSymbolAddress((void**)&pWp, g_Wp);
    cudaGetSymbolAddress((void**)&pQh, g_Qh);
    cudaGetSymbolAddress((void**)&pKh, g_Kh);
    cudaGetSymbolAddress((void**)&pVh, g_Vph);

    cudaFuncSetAttribute(tc_gemm_1p_kernel,
                         cudaFuncAttributeMaxDynamicSharedMemorySize, F_SMEM);
    cudaFuncSetAttribute(attn_colsum_tc,
                         cudaFuncAttributeMaxDynamicSharedMemorySize, CS_SMEM);
    cudaFuncSetAttribute(attn_av_tc,
                         cudaFuncAttributeMaxDynamicSharedMemorySize, AV_SMEM);
    cudaFuncSetAttribute(sx_kernel,
                         cudaFuncAttributeMaxDynamicSharedMemorySize, 65536);

    const int n4 = MTOT * DD / 4;
    const dim3 t256(256);
    const int npack = (DD / 2) * DD;
    const dim3 gGemm(DD / 128, MTOT / 128, 1);
    const dim3 gGemmQK(DD / 128, MTOT / 128, 2);

    // All fp32->fp16 conversions and W packs, batched
    tof16_batch<<<dim3((n4 + 255) / 256, 3), t256>>>(
        x_q, x_k, x_v, pAh, pXk, pXv, n4);
    pack_w_batch<<<dim3((npack + 255) / 256, 4), t256>>>(Wq, Wk, Wv, Wo, pWp);

    // Q + K projections in one launch (z=0: Q scaled log2e/32; z=1: K)
    tc_gemm_1p_kernel<<<gGemmQK, 256, F_SMEM>>>(
        pAh, pWp, bq, nullptr, pQh, nullptr, nullptr, SCALE_Q, 1,
        pXk, bk, pKh, 1.0f);

    // zinv = 1 / column-softmax sums (needs only Qh, Kh)
    attn_colsum_tc<<<dim3(8, BB * HH), 256, CS_SMEM>>>(pQh, pKh, pZi);

    // Exact Sv via commuted identity: Sv = (sum_k x_v zi) @ Wv + bv * sum(zi)
    sumz_kernel<<<BB * HH, 256>>>(pZi, pSz);
    sx_kernel<<<dim3(BB, 16), 256, 65536>>>(x_v, pZi, pSx);
    sv_kernel<<<BB * HH, 256>>>(pSx, Wv, bv, pSz, pSv);

    // V projection fused with Vp pack (mode 2): writes 1024*V/Z k-pairs
    tc_gemm_1p_kernel<<<gGemm, 256, F_SMEM>>>(
        pXv, pWp + 2 * WPS, bv, nullptr, nullptr, pZi, pVh, 1.0f, 2,
        nullptr, nullptr, nullptr, 0.0f);

    // AV -> fp16 attention output in g_Ah
    attn_av_tc<<<dim3(16, BB * HH), 256, AV_SMEM>>>(pQh, pKh, pVh, pSv, pAh);

    // Output projection (mode 0) -> d_out
    tc_gemm_1p_kernel<<<gGemm, 256, F_SMEM>>>(
        pAh, pWp + 3 * WPS, bo, (float*)d_out, nullptr, nullptr, nullptr, 1.0f, 0,
        nullptr, nullptr, nullptr, 0.0f);
}